// round 1
// baseline (speedup 1.0000x reference)
#include <cuda_runtime.h>
#include <math.h>

#define NB 32
#define NT 1024
#define NC 768
#define ND 64

// scratch: q,k stored transposed [b][d][t]; v natural [b][t][d]
__device__ float g_qT[NB * ND * NT];
__device__ float g_kT[NB * ND * NT];
__device__ float g_v [NB * NT * ND];

// XOR swizzle at float4 granularity for the k/p shared tile:
// row d (0..63), quad q (0..15) -> float index
__device__ __forceinline__ int ksw(int d, int q) {
    return (d * 16 + (q ^ (d & 15))) * 4;
}

// ---------------------------------------------------------------------------
// QKV projection + RoPE.  grid (256, 3), 256 threads.
// Block computes 128 rows x 64 cols of one of q/k/v. Thread micro-tile 8x4.
// q,k get RoPE applied and are written transposed ([b][d][t]) via an smem
// transpose so the attention kernel loads both S-GEMM operands natively.
// ---------------------------------------------------------------------------
__global__ __launch_bounds__(256) void qkv_kernel(
    const float* __restrict__ x, const float* __restrict__ Wq,
    const float* __restrict__ Wk, const float* __restrict__ Wv)
{
    __shared__ float smbuf[64 * 132];            // 33792 B, reused by epilogue
    float (*x_t)[132] = (float (*)[132])smbuf;   // [32][132]  (x tile, transposed [k][m])
    float* w_t = smbuf + 32 * 132;               // [32][64]

    const int mat = blockIdx.y;
    const float* __restrict__ W = (mat == 0) ? Wq : (mat == 1) ? Wk : Wv;
    const int m0 = blockIdx.x * 128;
    const int tid = threadIdx.x;
    const int tx = tid & 15, ty = tid >> 4;
    const int c0 = tx * 4;

    float acc[8][4];
#pragma unroll
    for (int i = 0; i < 8; i++)
#pragma unroll
        for (int j = 0; j < 4; j++) acc[i][j] = 0.f;

    for (int k0 = 0; k0 < NC; k0 += 32) {
        // load x tile 128x32, store transposed [k][m]
#pragma unroll
        for (int ch = 0; ch < 4; ch++) {
            int idx = tid + ch * 256;
            int row = idx >> 3;     // 0..127
            int kq  = idx & 7;      // 8 quads of k
            float4 xv = *(const float4*)(x + (size_t)(m0 + row) * NC + k0 + kq * 4);
            x_t[kq * 4 + 0][row] = xv.x;
            x_t[kq * 4 + 1][row] = xv.y;
            x_t[kq * 4 + 2][row] = xv.z;
            x_t[kq * 4 + 3][row] = xv.w;
        }
        // load W tile 32x64 natural
#pragma unroll
        for (int ch = 0; ch < 2; ch++) {
            int idx = tid + ch * 256;
            int row = idx >> 4;     // 0..31
            int cq  = idx & 15;
            *(float4*)&w_t[row * 64 + cq * 4] =
                *(const float4*)(W + (size_t)(k0 + row) * ND + cq * 4);
        }
        __syncthreads();
#pragma unroll
        for (int kk = 0; kk < 32; kk++) {
            float4 a0 = *(const float4*)&x_t[kk][ty * 8];
            float4 a1 = *(const float4*)&x_t[kk][ty * 8 + 4];
            float4 b4 = *(const float4*)&w_t[kk * 64 + c0];
            float av[8] = {a0.x, a0.y, a0.z, a0.w, a1.x, a1.y, a1.z, a1.w};
            float bv[4] = {b4.x, b4.y, b4.z, b4.w};
#pragma unroll
            for (int i = 0; i < 8; i++)
#pragma unroll
                for (int j = 0; j < 4; j++)
                    acc[i][j] = fmaf(av[i], bv[j], acc[i][j]);
        }
        __syncthreads();
    }

    if (mat < 2) {
        // RoPE in registers. pair index pi -> freq = 10000^(-pi/32)
#pragma unroll
        for (int i = 0; i < 8; i++) {
            float tpos = (float)((m0 + ty * 8 + i) & (NT - 1));
#pragma unroll
            for (int p = 0; p < 2; p++) {
                int pi = (c0 >> 1) + p;
                float freq = expf((float)(2 * pi) * (-9.210340371976184f / (float)ND));
                float sv, cv;
                sincosf(tpos * freq, &sv, &cv);
                float te = acc[i][2 * p], to = acc[i][2 * p + 1];
                acc[i][2 * p]     = te * cv - to * sv;
                acc[i][2 * p + 1] = te * sv + to * cv;
            }
        }
        // transpose 128x64 tile via smem, store as [b][d][t] coalesced
        float* t_s = smbuf;  // [64][132]
#pragma unroll
        for (int i = 0; i < 8; i++)
#pragma unroll
            for (int j = 0; j < 4; j++)
                t_s[(c0 + j) * 132 + ty * 8 + i] = acc[i][j];
        __syncthreads();
        float* outT = (mat == 0) ? g_qT : g_kT;
        const int bb = m0 >> 10;
        const int t0 = m0 & (NT - 1);
#pragma unroll
        for (int ch = 0; ch < 8; ch++) {
            int idx = tid + ch * 256;
            int crow = idx >> 5;    // 0..63 (d)
            int mq   = idx & 31;    // 32 quads of t
            float4 v4 = *(const float4*)&t_s[crow * 132 + mq * 4];
            *(float4*)(outT + (size_t)(bb * ND + crow) * NT + t0 + mq * 4) = v4;
        }
    } else {
        // v: natural [b][t][d]
#pragma unroll
        for (int i = 0; i < 8; i++) {
            float4 v4 = make_float4(acc[i][0], acc[i][1], acc[i][2], acc[i][3]);
            *(float4*)(g_v + (size_t)(m0 + ty * 8 + i) * ND + c0) = v4;
        }
    }
}

// ---------------------------------------------------------------------------
// Flash attention (causal, online softmax). grid (16, 32), 256 threads.
// BM=BN=64, d=64. Thread micro-tile 4x4. 48 KB static smem exactly.
// kp_s is swizzled (ksw) and reused for both K tile and transposed P tile.
// ---------------------------------------------------------------------------
__global__ __launch_bounds__(256) void attn_kernel(float* __restrict__ out) {
    __shared__ float q_s[64 * 64];   // [d][r]
    __shared__ float kp_s[64 * 64];  // swizzled: K as [d][c], then P as [s][r]
    __shared__ float v_s[64 * 64];   // [s][c]

    const int b  = blockIdx.y;
    const int qt = blockIdx.x;
    const int q0 = qt * 64;
    const int tid = threadIdx.x;
    const int tx = tid & 15, ty = tid >> 4;
    const int r0 = ty * 4, c0 = tx * 4;
    const float scale = 1.f / sqrtf((float)NC);

    // load q tile [d][r] directly from transposed layout, fold in scale
#pragma unroll
    for (int ch = 0; ch < 4; ch++) {
        int idx = tid + ch * 256;
        int drow = idx >> 4;
        int cq   = idx & 15;
        float4 qv = *(const float4*)(g_qT + (size_t)(b * ND + drow) * NT + q0 + cq * 4);
        qv.x *= scale; qv.y *= scale; qv.z *= scale; qv.w *= scale;
        *(float4*)&q_s[drow * 64 + cq * 4] = qv;
    }

    float o[4][4];
    float m_r[4], l_r[4];
#pragma unroll
    for (int i = 0; i < 4; i++) {
        m_r[i] = -INFINITY; l_r[i] = 0.f;
#pragma unroll
        for (int j = 0; j < 4; j++) o[i][j] = 0.f;
    }

    for (int jt = 0; jt <= qt; jt++) {
        const int kv0 = jt * 64;
        __syncthreads();   // previous P-GEMM reads done (also covers q_s stores)
        // load K tile [d][c] (swizzled) and V tile [s][c]
#pragma unroll
        for (int ch = 0; ch < 4; ch++) {
            int idx = tid + ch * 256;
            int row = idx >> 4;
            int cq  = idx & 15;
            float4 kv = *(const float4*)(g_kT + (size_t)(b * ND + row) * NT + kv0 + cq * 4);
            *(float4*)&kp_s[ksw(row, cq)] = kv;
            float4 vv = *(const float4*)(g_v + (size_t)(b * NT + kv0 + row) * ND + cq * 4);
            *(float4*)&v_s[row * 64 + cq * 4] = vv;
        }
        __syncthreads();

        // S = q @ k^T  (scaled)
        float s[4][4];
#pragma unroll
        for (int i = 0; i < 4; i++)
#pragma unroll
            for (int j = 0; j < 4; j++) s[i][j] = 0.f;

#pragma unroll 8
        for (int d = 0; d < 64; d++) {
            float4 qv = *(const float4*)&q_s[d * 64 + r0];
            float4 kv = *(const float4*)&kp_s[ksw(d, tx)];
            float qa[4] = {qv.x, qv.y, qv.z, qv.w};
            float ka[4] = {kv.x, kv.y, kv.z, kv.w};
#pragma unroll
            for (int i = 0; i < 4; i++)
#pragma unroll
                for (int j = 0; j < 4; j++)
                    s[i][j] = fmaf(qa[i], ka[j], s[i][j]);
        }

        if (jt == qt) {   // causal mask on diagonal tile
#pragma unroll
            for (int i = 0; i < 4; i++)
#pragma unroll
                for (int j = 0; j < 4; j++)
                    if (c0 + j > r0 + i) s[i][j] = -INFINITY;
        }

        // online softmax (rows owned by tx-group of 16 lanes, in-warp shfl)
        float p[4][4], alpha[4];
#pragma unroll
        for (int i = 0; i < 4; i++) {
            float mx = fmaxf(fmaxf(s[i][0], s[i][1]), fmaxf(s[i][2], s[i][3]));
#pragma unroll
            for (int w = 8; w >= 1; w >>= 1)
                mx = fmaxf(mx, __shfl_xor_sync(0xffffffffu, mx, w));
            float mn = fmaxf(m_r[i], mx);
            alpha[i] = __expf(m_r[i] - mn);
            m_r[i] = mn;
            float sum = 0.f;
#pragma unroll
            for (int j = 0; j < 4; j++) {
                p[i][j] = __expf(s[i][j] - mn);
                sum += p[i][j];
            }
#pragma unroll
            for (int w = 8; w >= 1; w >>= 1)
                sum += __shfl_xor_sync(0xffffffffu, sum, w);
            l_r[i] = l_r[i] * alpha[i] + sum;
#pragma unroll
            for (int j = 0; j < 4; j++) o[i][j] *= alpha[i];
        }

        __syncthreads();   // all K reads done, kp_s can be repurposed for P
#pragma unroll
        for (int j = 0; j < 4; j++)
#pragma unroll
            for (int i = 0; i < 4; i++)
                kp_s[ksw(c0 + j, ty) + i] = p[i][j];   // P stored [s][r]
        __syncthreads();

        // O += P @ V
#pragma unroll 8
        for (int ss = 0; ss < 64; ss++) {
            float4 pv = *(const float4*)&kp_s[ksw(ss, ty)];
            float4 vv = *(const float4*)&v_s[ss * 64 + c0];
            float pa[4] = {pv.x, pv.y, pv.z, pv.w};
            float va[4] = {vv.x, vv.y, vv.z, vv.w};
#pragma unroll
            for (int i = 0; i < 4; i++)
#pragma unroll
                for (int j = 0; j < 4; j++)
                    o[i][j] = fmaf(pa[i], va[j], o[i][j]);
        }
    }

#pragma unroll
    for (int i = 0; i < 4; i++) {
        float inv = 1.f / l_r[i];
        float4 ov = make_float4(o[i][0] * inv, o[i][1] * inv, o[i][2] * inv, o[i][3] * inv);
        *(float4*)(out + (size_t)(b * NT + q0 + r0 + i) * ND + c0) = ov;
    }
}

extern "C" void kernel_launch(void* const* d_in, const int* in_sizes, int n_in,
                              void* d_out, int out_size) {
    (void)in_sizes; (void)n_in; (void)out_size;
    const float* x  = (const float*)d_in[0];
    const float* Wq = (const float*)d_in[1];
    const float* Wk = (const float*)d_in[2];
    const float* Wv = (const float*)d_in[3];
    float* out = (float*)d_out;

    qkv_kernel<<<dim3(256, 3), 256>>>(x, Wq, Wk, Wv);
    attn_kernel<<<dim3(16, 32), 256>>>(out);
}

// round 2
// speedup vs baseline: 1.0723x; 1.0723x over previous
#include <cuda_runtime.h>
#include <math.h>

#define NB 32
#define NT 1024
#define NC 768
#define ND 64

typedef unsigned long long ull;

// ---- packed fp32x2 helpers (sm_103a FFMA2 path; ptxas won't emit these) ----
__device__ __forceinline__ ull bcast2(float a) {
    ull r; asm("mov.b64 %0, {%1, %1};" : "=l"(r) : "f"(a)); return r;
}
__device__ __forceinline__ ull pack2(float lo, float hi) {
    ull r; asm("mov.b64 %0, {%1, %2};" : "=l"(r) : "f"(lo), "f"(hi)); return r;
}
__device__ __forceinline__ void fma2(ull& d, ull a, ull b) {
    asm("fma.rn.f32x2 %0, %1, %2, %0;" : "+l"(d) : "l"(a), "l"(b));
}
__device__ __forceinline__ void mul2(ull& d, ull a, ull b) {
    asm("mul.rn.f32x2 %0, %1, %2;" : "=l"(d) : "l"(a), "l"(b));
}
__device__ __forceinline__ float2 unpk(ull v) {
    float x, y; asm("mov.b64 {%0, %1}, %2;" : "=f"(x), "=f"(y) : "l"(v));
    return make_float2(x, y);
}

// scratch: q,k stored transposed [b][d][t]; v natural [b][t][d]
__device__ float g_qT[NB * ND * NT];
__device__ float g_kT[NB * ND * NT];
__device__ float g_v [NB * NT * ND];

// XOR swizzle at float4 granularity for the k/p shared tile
__device__ __forceinline__ int ksw(int d, int q) {
    return (d * 16 + (q ^ (d & 15))) * 4;
}

// ---------------------------------------------------------------------------
// QKV projection + RoPE.  grid (256, 3), 256 threads.
// Thread micro-tile 8x4, accumulators packed as row-pairs (i-packing):
// a-pairs come free from float4 LDS; b is broadcast (1 MOV each).
// ---------------------------------------------------------------------------
__global__ __launch_bounds__(256) void qkv_kernel(
    const float* __restrict__ x, const float* __restrict__ Wq,
    const float* __restrict__ Wk, const float* __restrict__ Wv)
{
    __shared__ float smbuf[64 * 132];            // 33792 B, reused by epilogue
    float (*x_t)[132] = (float (*)[132])smbuf;   // [32][132]  (x tile, [k][m])
    float* w_t = smbuf + 32 * 132;               // [32][64]

    const int mat = blockIdx.y;
    const float* __restrict__ W = (mat == 0) ? Wq : (mat == 1) ? Wk : Wv;
    const int m0 = blockIdx.x * 128;
    const int tid = threadIdx.x;
    const int tx = tid & 15, ty = tid >> 4;
    const int c0 = tx * 4;

    ull acc2[4][4];   // [row-pair][col]; pair = (row 2ip, row 2ip+1)
#pragma unroll
    for (int i = 0; i < 4; i++)
#pragma unroll
        for (int j = 0; j < 4; j++) acc2[i][j] = 0ULL;

    for (int k0 = 0; k0 < NC; k0 += 32) {
#pragma unroll
        for (int ch = 0; ch < 4; ch++) {
            int idx = tid + ch * 256;
            int row = idx >> 3;
            int kq  = idx & 7;
            float4 xv = *(const float4*)(x + (size_t)(m0 + row) * NC + k0 + kq * 4);
            x_t[kq * 4 + 0][row] = xv.x;
            x_t[kq * 4 + 1][row] = xv.y;
            x_t[kq * 4 + 2][row] = xv.z;
            x_t[kq * 4 + 3][row] = xv.w;
        }
#pragma unroll
        for (int ch = 0; ch < 2; ch++) {
            int idx = tid + ch * 256;
            int row = idx >> 4;
            int cq  = idx & 15;
            *(float4*)&w_t[row * 64 + cq * 4] =
                *(const float4*)(W + (size_t)(k0 + row) * ND + cq * 4);
        }
        __syncthreads();
#pragma unroll
        for (int kk = 0; kk < 32; kk++) {
            float4 a0 = *(const float4*)&x_t[kk][ty * 8];
            float4 a1 = *(const float4*)&x_t[kk][ty * 8 + 4];
            float4 b4 = *(const float4*)&w_t[kk * 64 + c0];
            ull ap[4] = {pack2(a0.x, a0.y), pack2(a0.z, a0.w),
                         pack2(a1.x, a1.y), pack2(a1.z, a1.w)};
            ull bb[4] = {bcast2(b4.x), bcast2(b4.y), bcast2(b4.z), bcast2(b4.w)};
#pragma unroll
            for (int ip = 0; ip < 4; ip++)
#pragma unroll
                for (int j = 0; j < 4; j++)
                    fma2(acc2[ip][j], ap[ip], bb[j]);
        }
        __syncthreads();
    }

    // unpack to scalar rows
    float acc[8][4];
#pragma unroll
    for (int ip = 0; ip < 4; ip++)
#pragma unroll
        for (int j = 0; j < 4; j++) {
            float2 t = unpk(acc2[ip][j]);
            acc[2 * ip][j]     = t.x;
            acc[2 * ip + 1][j] = t.y;
        }

    if (mat < 2) {
        // RoPE in registers
#pragma unroll
        for (int i = 0; i < 8; i++) {
            float tpos = (float)((m0 + ty * 8 + i) & (NT - 1));
#pragma unroll
            for (int p = 0; p < 2; p++) {
                int pi = (c0 >> 1) + p;
                float freq = expf((float)(2 * pi) * (-9.210340371976184f / (float)ND));
                float sv, cv;
                sincosf(tpos * freq, &sv, &cv);
                float te = acc[i][2 * p], to = acc[i][2 * p + 1];
                acc[i][2 * p]     = te * cv - to * sv;
                acc[i][2 * p + 1] = te * sv + to * cv;
            }
        }
        // transpose via smem, store [b][d][t] coalesced
        float* t_s = smbuf;  // [64][132]
#pragma unroll
        for (int i = 0; i < 8; i++)
#pragma unroll
            for (int j = 0; j < 4; j++)
                t_s[(c0 + j) * 132 + ty * 8 + i] = acc[i][j];
        __syncthreads();
        float* outT = (mat == 0) ? g_qT : g_kT;
        const int bb = m0 >> 10;
        const int t0 = m0 & (NT - 1);
#pragma unroll
        for (int ch = 0; ch < 8; ch++) {
            int idx = tid + ch * 256;
            int crow = idx >> 5;
            int mq   = idx & 31;
            float4 v4 = *(const float4*)&t_s[crow * 132 + mq * 4];
            *(float4*)(outT + (size_t)(bb * ND + crow) * NT + t0 + mq * 4) = v4;
        }
    } else {
#pragma unroll
        for (int i = 0; i < 8; i++) {
            float4 v4 = make_float4(acc[i][0], acc[i][1], acc[i][2], acc[i][3]);
            *(float4*)(g_v + (size_t)(m0 + ty * 8 + i) * ND + c0) = v4;
        }
    }
}

// ---------------------------------------------------------------------------
// Flash attention (causal, online softmax). grid (16, 32), 256 threads.
// BM=BN=64, thread micro-tile 4x4 with i-packed f32x2 accumulators.
// Descending-qt schedule: heaviest CTAs first -> shorter tail.
// ---------------------------------------------------------------------------
__global__ __launch_bounds__(256) void attn_kernel(float* __restrict__ out) {
    __shared__ float q_s[64 * 64];   // [d][r]
    __shared__ float kp_s[64 * 64];  // swizzled: K as [d][c], then P as [s][r]
    __shared__ float v_s[64 * 64];   // [s][c]

    const int b  = blockIdx.y;
    const int qt = (int)gridDim.x - 1 - (int)blockIdx.x;   // heavy tiles first
    const int q0 = qt * 64;
    const int tid = threadIdx.x;
    const int tx = tid & 15, ty = tid >> 4;
    const int r0 = ty * 4, c0 = tx * 4;
    const float scale = 1.f / sqrtf((float)NC);

#pragma unroll
    for (int ch = 0; ch < 4; ch++) {
        int idx = tid + ch * 256;
        int drow = idx >> 4;
        int cq   = idx & 15;
        float4 qv = *(const float4*)(g_qT + (size_t)(b * ND + drow) * NT + q0 + cq * 4);
        qv.x *= scale; qv.y *= scale; qv.z *= scale; qv.w *= scale;
        *(float4*)&q_s[drow * 64 + cq * 4] = qv;
    }

    ull o2[2][4];                 // [row-pair][col]
    float m_r[4], l_r[4];
#pragma unroll
    for (int i = 0; i < 4; i++) { m_r[i] = -INFINITY; l_r[i] = 0.f; }
#pragma unroll
    for (int ip = 0; ip < 2; ip++)
#pragma unroll
        for (int j = 0; j < 4; j++) o2[ip][j] = 0ULL;

    for (int jt = 0; jt <= qt; jt++) {
        const int kv0 = jt * 64;
        __syncthreads();   // previous P-GEMM reads done (also covers q_s stores)
#pragma unroll
        for (int ch = 0; ch < 4; ch++) {
            int idx = tid + ch * 256;
            int row = idx >> 4;
            int cq  = idx & 15;
            float4 kv = *(const float4*)(g_kT + (size_t)(b * ND + row) * NT + kv0 + cq * 4);
            *(float4*)&kp_s[ksw(row, cq)] = kv;
            float4 vv = *(const float4*)(g_v + (size_t)(b * NT + kv0 + row) * ND + cq * 4);
            *(float4*)&v_s[row * 64 + cq * 4] = vv;
        }
        __syncthreads();

        // S = q @ k^T (scaled). i-packed: q pairs free from LDS.128, k broadcast.
        ull s2[2][4];
#pragma unroll
        for (int ip = 0; ip < 2; ip++)
#pragma unroll
            for (int j = 0; j < 4; j++) s2[ip][j] = 0ULL;

#pragma unroll 8
        for (int d = 0; d < 64; d++) {
            float4 qv = *(const float4*)&q_s[d * 64 + r0];
            float4 kv = *(const float4*)&kp_s[ksw(d, tx)];
            ull qp[2] = {pack2(qv.x, qv.y), pack2(qv.z, qv.w)};
            ull kb[4] = {bcast2(kv.x), bcast2(kv.y), bcast2(kv.z), bcast2(kv.w)};
#pragma unroll
            for (int ip = 0; ip < 2; ip++)
#pragma unroll
                for (int j = 0; j < 4; j++)
                    fma2(s2[ip][j], qp[ip], kb[j]);
        }

        // unpack s
        float s[4][4];
#pragma unroll
        for (int ip = 0; ip < 2; ip++)
#pragma unroll
            for (int j = 0; j < 4; j++) {
                float2 t = unpk(s2[ip][j]);
                s[2 * ip][j]     = t.x;
                s[2 * ip + 1][j] = t.y;
            }

        if (jt == qt) {   // causal mask on diagonal tile
#pragma unroll
            for (int i = 0; i < 4; i++)
#pragma unroll
                for (int j = 0; j < 4; j++)
                    if (c0 + j > r0 + i) s[i][j] = -INFINITY;
        }

        // online softmax (rows owned by 16-lane tx group, in-warp shfl)
        float p[4][4], alpha[4];
#pragma unroll
        for (int i = 0; i < 4; i++) {
            float mx = fmaxf(fmaxf(s[i][0], s[i][1]), fmaxf(s[i][2], s[i][3]));
#pragma unroll
            for (int w = 8; w >= 1; w >>= 1)
                mx = fmaxf(mx, __shfl_xor_sync(0xffffffffu, mx, w));
            float mn = fmaxf(m_r[i], mx);
            alpha[i] = __expf(m_r[i] - mn);
            m_r[i] = mn;
            float sum = 0.f;
#pragma unroll
            for (int j = 0; j < 4; j++) {
                p[i][j] = __expf(s[i][j] - mn);
                sum += p[i][j];
            }
#pragma unroll
            for (int w = 8; w >= 1; w >>= 1)
                sum += __shfl_xor_sync(0xffffffffu, sum, w);
            l_r[i] = l_r[i] * alpha[i] + sum;
        }
        // rescale o (packed along i)
#pragma unroll
        for (int ip = 0; ip < 2; ip++) {
            ull al = pack2(alpha[2 * ip], alpha[2 * ip + 1]);
#pragma unroll
            for (int j = 0; j < 4; j++) mul2(o2[ip][j], o2[ip][j], al);
        }

        __syncthreads();   // all K reads done, kp_s repurposed for P
#pragma unroll
        for (int j = 0; j < 4; j++)
#pragma unroll
            for (int i = 0; i < 4; i++)
                kp_s[ksw(c0 + j, ty) + i] = p[i][j];   // P stored [s][r]
        __syncthreads();

        // O += P @ V. p pairs free from LDS.128 (along r), v broadcast.
#pragma unroll 8
        for (int ss = 0; ss < 64; ss++) {
            float4 pv = *(const float4*)&kp_s[ksw(ss, ty)];
            float4 vv = *(const float4*)&v_s[ss * 64 + c0];
            ull pp[2] = {pack2(pv.x, pv.y), pack2(pv.z, pv.w)};
            ull vb[4] = {bcast2(vv.x), bcast2(vv.y), bcast2(vv.z), bcast2(vv.w)};
#pragma unroll
            for (int ip = 0; ip < 2; ip++)
#pragma unroll
                for (int j = 0; j < 4; j++)
                    fma2(o2[ip][j], pp[ip], vb[j]);
        }
    }

#pragma unroll
    for (int ip = 0; ip < 2; ip++) {
        float inv0 = 1.f / l_r[2 * ip];
        float inv1 = 1.f / l_r[2 * ip + 1];
        float4 ov0, ov1;
        float2 t0 = unpk(o2[ip][0]);
        float2 t1 = unpk(o2[ip][1]);
        float2 t2 = unpk(o2[ip][2]);
        float2 t3 = unpk(o2[ip][3]);
        ov0 = make_float4(t0.x * inv0, t1.x * inv0, t2.x * inv0, t3.x * inv0);
        ov1 = make_float4(t0.y * inv1, t1.y * inv1, t2.y * inv1, t3.y * inv1);
        *(float4*)(out + (size_t)(b * NT + q0 + r0 + 2 * ip) * ND + c0)     = ov0;
        *(float4*)(out + (size_t)(b * NT + q0 + r0 + 2 * ip + 1) * ND + c0) = ov1;
    }
}

extern "C" void kernel_launch(void* const* d_in, const int* in_sizes, int n_in,
                              void* d_out, int out_size) {
    (void)in_sizes; (void)n_in; (void)out_size;
    const float* x  = (const float*)d_in[0];
    const float* Wq = (const float*)d_in[1];
    const float* Wk = (const float*)d_in[2];
    const float* Wv = (const float*)d_in[3];
    float* out = (float*)d_out;

    qkv_kernel<<<dim3(256, 3), 256>>>(x, Wq, Wk, Wv);
    attn_kernel<<<dim3(16, 32), 256>>>(out);
}

// round 4
// speedup vs baseline: 1.4030x; 1.3084x over previous
#include <cuda_runtime.h>
#include <cuda_bf16.h>
#include <math.h>
#include <cstdint>

#define NB 32
#define NT 1024
#define NC 768
#define ND 64

typedef unsigned long long ull;

// ---- packed fp32x2 helpers ----
__device__ __forceinline__ ull bcast2(float a) {
    ull r; asm("mov.b64 %0, {%1, %1};" : "=l"(r) : "f"(a)); return r;
}
__device__ __forceinline__ ull pack2(float lo, float hi) {
    ull r; asm("mov.b64 %0, {%1, %2};" : "=l"(r) : "f"(lo), "f"(hi)); return r;
}
__device__ __forceinline__ void fma2(ull& d, ull a, ull b) {
    asm("fma.rn.f32x2 %0, %1, %2, %0;" : "+l"(d) : "l"(a), "l"(b));
}
__device__ __forceinline__ void mul2(ull& d, ull a, ull b) {
    asm("mul.rn.f32x2 %0, %1, %2;" : "=l"(d) : "l"(a), "l"(b));
}
__device__ __forceinline__ float2 unpk(ull v) {
    float x, y; asm("mov.b64 {%0, %1}, %2;" : "=f"(x), "=f"(y) : "l"(v));
    return make_float2(x, y);
}
// pack two f32 -> bf16x2 (first arg = low half)
__device__ __forceinline__ uint32_t pack_bf2(float lo, float hi) {
    uint32_t r; asm("cvt.rn.bf16x2.f32 %0, %1, %2;" : "=r"(r) : "f"(hi), "f"(lo)); return r;
}

// HMMA m16n8k16 bf16, fp32 accum (portable, sm_80+)
__device__ __forceinline__ void mma16816(float* c, const uint32_t* a, const uint32_t* b) {
    asm volatile(
        "mma.sync.aligned.m16n8k16.row.col.f32.bf16.bf16.f32 "
        "{%0,%1,%2,%3}, {%4,%5,%6,%7}, {%8,%9}, {%0,%1,%2,%3};"
        : "+f"(c[0]), "+f"(c[1]), "+f"(c[2]), "+f"(c[3])
        : "r"(a[0]), "r"(a[1]), "r"(a[2]), "r"(a[3]), "r"(b[0]), "r"(b[1]));
}

// scratch
__device__ float g_qT[NB * ND * NT];
__device__ float g_kT[NB * ND * NT];
__device__ float g_v [NB * NT * ND];
// W^T in bf16 hi/lo: [mat][n=64][k=768] row-major
__device__ __align__(16) __nv_bfloat16 g_Bh[3 * 64 * NC];
__device__ __align__(16) __nv_bfloat16 g_Bl[3 * 64 * NC];

// XOR swizzle at float4 granularity (attn shared tile)
__device__ __forceinline__ int ksw(int d, int q) {
    return (d * 16 + (q ^ (d & 15))) * 4;
}

// ---------------------------------------------------------------------------
// W conversion: fp32 [768][64] -> bf16 hi/lo W^T [mat][64][768]
// ---------------------------------------------------------------------------
__global__ __launch_bounds__(256) void wconv_kernel(
    const float* __restrict__ Wq, const float* __restrict__ Wk, const float* __restrict__ Wv)
{
    int idx = blockIdx.x * 256 + threadIdx.x;   // 0..147455
    int mat = idx / 49152;
    int r = idx - mat * 49152;
    int n = r / NC;
    int k = r - n * NC;
    const float* W = (mat == 0) ? Wq : (mat == 1) ? Wk : Wv;
    float v = W[k * ND + n];
    __nv_bfloat16 h = __float2bfloat16(v);
    __nv_bfloat16 l = __float2bfloat16(v - __bfloat162float(h));
    g_Bh[idx] = h;
    g_Bl[idx] = l;
}

// ---------------------------------------------------------------------------
// QKV GEMM via mma.sync bf16-split + RoPE epilogue.
// grid 768 (bid = mtile*3 + mat so x-tile sharers are wave-adjacent), 256 thr.
// Warp layout 4(M)x2(N); warp tile 32x32 = 2x4 m16n8k16 tiles.
// smem pitch 80 B -> conflict-free b32 fragment loads. 33792 B static.
// ---------------------------------------------------------------------------
#define OFF_AH 0
#define OFF_AL 10240
#define OFF_BH 20480
#define OFF_BL 25600

__global__ __launch_bounds__(256) void qkv_mma(const float* __restrict__ x)
{
    __shared__ __align__(16) char sm[33792];

    const int tid = threadIdx.x;
    const int lane = tid & 31, w = tid >> 5;
    const int warpM = w & 3, warpN = w >> 2;
    const int g = lane >> 2, qd = lane & 3;
    const int bid = blockIdx.x;
    const int mat = bid % 3;
    const int m0 = (bid / 3) * 128;

    float acc[2][4][4];
#pragma unroll
    for (int mt = 0; mt < 2; mt++)
#pragma unroll
        for (int nt = 0; nt < 4; nt++)
#pragma unroll
            for (int i = 0; i < 4; i++) acc[mt][nt][i] = 0.f;

    const int am = tid >> 1, kh = tid & 1;
    const float* xrow = x + (size_t)(m0 + am) * NC + kh * 16;
    const int brow = tid >> 2, bq = tid & 3;
    const __nv_bfloat16* bsrcH = g_Bh + mat * 49152 + brow * NC;
    const __nv_bfloat16* bsrcL = g_Bl + mat * 49152 + brow * NC;

    for (int c = 0; c < 24; c++) {
        __syncthreads();
        // ---- A: load 16 fp32, split to bf16 hi/lo, store pitch-80 ----
#pragma unroll
        for (int gg = 0; gg < 2; gg++) {
            float4 a = *(const float4*)(xrow + c * 32 + gg * 8);
            float4 b = *(const float4*)(xrow + c * 32 + gg * 8 + 4);
            uint32_t h0 = pack_bf2(a.x, a.y);
            uint32_t h1 = pack_bf2(a.z, a.w);
            uint32_t h2 = pack_bf2(b.x, b.y);
            uint32_t h3 = pack_bf2(b.z, b.w);
            uint32_t l0 = pack_bf2(a.x - __uint_as_float(h0 << 16), a.y - __uint_as_float(h0 & 0xffff0000u));
            uint32_t l1 = pack_bf2(a.z - __uint_as_float(h1 << 16), a.w - __uint_as_float(h1 & 0xffff0000u));
            uint32_t l2 = pack_bf2(b.x - __uint_as_float(h2 << 16), b.y - __uint_as_float(h2 & 0xffff0000u));
            uint32_t l3 = pack_bf2(b.z - __uint_as_float(h3 << 16), b.w - __uint_as_float(h3 & 0xffff0000u));
            int off = am * 80 + kh * 32 + gg * 16;
            *(uint4*)(sm + OFF_AH + off) = make_uint4(h0, h1, h2, h3);
            *(uint4*)(sm + OFF_AL + off) = make_uint4(l0, l1, l2, l3);
        }
        // ---- B: copy pre-converted W^T tile rows (64 x 32 bf16) ----
        {
            int off = brow * 80 + bq * 16;
            *(uint4*)(sm + OFF_BH + off) = *(const uint4*)(bsrcH + c * 32 + bq * 8);
            *(uint4*)(sm + OFF_BL + off) = *(const uint4*)(bsrcL + c * 32 + bq * 8);
        }
        __syncthreads();

#pragma unroll
        for (int ks = 0; ks < 2; ks++) {
            const int kb = ks * 32 + qd * 4;   // byte offset within row
            uint32_t ah[2][4], al[2][4];
#pragma unroll
            for (int mt = 0; mt < 2; mt++) {
                int r = warpM * 32 + mt * 16 + g;
                int o0 = r * 80 + kb;
                int o1 = o0 + 8 * 80;
                ah[mt][0] = *(const uint32_t*)(sm + OFF_AH + o0);
                ah[mt][1] = *(const uint32_t*)(sm + OFF_AH + o1);
                ah[mt][2] = *(const uint32_t*)(sm + OFF_AH + o0 + 16);
                ah[mt][3] = *(const uint32_t*)(sm + OFF_AH + o1 + 16);
                al[mt][0] = *(const uint32_t*)(sm + OFF_AL + o0);
                al[mt][1] = *(const uint32_t*)(sm + OFF_AL + o1);
                al[mt][2] = *(const uint32_t*)(sm + OFF_AL + o0 + 16);
                al[mt][3] = *(const uint32_t*)(sm + OFF_AL + o1 + 16);
            }
#pragma unroll
            for (int nt = 0; nt < 4; nt++) {
                int n = warpN * 32 + nt * 8 + g;
                int ob = n * 80 + kb;
                uint32_t bh[2] = {*(const uint32_t*)(sm + OFF_BH + ob),
                                  *(const uint32_t*)(sm + OFF_BH + ob + 16)};
                uint32_t bl[2] = {*(const uint32_t*)(sm + OFF_BL + ob),
                                  *(const uint32_t*)(sm + OFF_BL + ob + 16)};
#pragma unroll
                for (int mt = 0; mt < 2; mt++) {
                    mma16816(acc[mt][nt], ah[mt], bh);
                    mma16816(acc[mt][nt], ah[mt], bl);
                    mma16816(acc[mt][nt], al[mt], bh);
                }
            }
        }
    }
    __syncthreads();   // all mma smem reads done

    if (mat < 2) {
        // RoPE in registers (thread owns adjacent even/odd column pairs)
        float* t_s = (float*)sm;   // [64][132]
#pragma unroll
        for (int nt = 0; nt < 4; nt++) {
            int c0 = warpN * 32 + nt * 8 + qd * 2;
            int pi = c0 >> 1;
            float freq = expf((float)(2 * pi) * (-9.210340371976184f / (float)ND));
#pragma unroll
            for (int mt = 0; mt < 2; mt++) {
                int ml0 = warpM * 32 + mt * 16 + g;
                int ml1 = ml0 + 8;
                float sv, cv;
                sincosf((float)((m0 + ml0) & (NT - 1)) * freq, &sv, &cv);
                float e0 = acc[mt][nt][0], o0v = acc[mt][nt][1];
                float re0 = e0 * cv - o0v * sv;
                float ro0 = e0 * sv + o0v * cv;
                sincosf((float)((m0 + ml1) & (NT - 1)) * freq, &sv, &cv);
                float e1 = acc[mt][nt][2], o1v = acc[mt][nt][3];
                float re1 = e1 * cv - o1v * sv;
                float ro1 = e1 * sv + o1v * cv;
                t_s[c0 * 132 + ml0]       = re0;
                t_s[(c0 + 1) * 132 + ml0] = ro0;
                t_s[c0 * 132 + ml1]       = re1;
                t_s[(c0 + 1) * 132 + ml1] = ro1;
            }
        }
        __syncthreads();
        float* outT = (mat == 0) ? g_qT : g_kT;
        const int bb = m0 >> 10;
        const int t0l = m0 & (NT - 1);
#pragma unroll
        for (int i = 0; i < 8; i++) {
            int idx = tid + i * 256;
            int crow = idx >> 5;
            int mq = idx & 31;
            float4 v4 = *(float4*)&t_s[crow * 132 + mq * 4];
            *(float4*)(outT + (size_t)(bb * ND + crow) * NT + t0l + mq * 4) = v4;
        }
    } else {
        // v: direct [b][t][d]
#pragma unroll
        for (int nt = 0; nt < 4; nt++) {
            int c0 = warpN * 32 + nt * 8 + qd * 2;
#pragma unroll
            for (int mt = 0; mt < 2; mt++) {
                int ml0 = warpM * 32 + mt * 16 + g;
                *(float2*)(g_v + (size_t)(m0 + ml0) * ND + c0) =
                    make_float2(acc[mt][nt][0], acc[mt][nt][1]);
                *(float2*)(g_v + (size_t)(m0 + ml0 + 8) * ND + c0) =
                    make_float2(acc[mt][nt][2], acc[mt][nt][3]);
            }
        }
    }
}

// ---------------------------------------------------------------------------
// Flash attention (causal, online softmax). grid (16, 32), 256 threads.
// Unchanged from round 2 (196us); tensorize next round.
// ---------------------------------------------------------------------------
__global__ __launch_bounds__(256) void attn_kernel(float* __restrict__ out) {
    __shared__ float q_s[64 * 64];
    __shared__ float kp_s[64 * 64];
    __shared__ float v_s[64 * 64];

    const int b  = blockIdx.y;
    const int qt = (int)gridDim.x - 1 - (int)blockIdx.x;
    const int q0 = qt * 64;
    const int tid = threadIdx.x;
    const int tx = tid & 15, ty = tid >> 4;
    const int r0 = ty * 4, c0 = tx * 4;
    const float scale = 1.f / sqrtf((float)NC);

#pragma unroll
    for (int ch = 0; ch < 4; ch++) {
        int idx = tid + ch * 256;
        int drow = idx >> 4;
        int cq   = idx & 15;
        float4 qv = *(const float4*)(g_qT + (size_t)(b * ND + drow) * NT + q0 + cq * 4);
        qv.x *= scale; qv.y *= scale; qv.z *= scale; qv.w *= scale;
        *(float4*)&q_s[drow * 64 + cq * 4] = qv;
    }

    ull o2[2][4];
    float m_r[4], l_r[4];
#pragma unroll
    for (int i = 0; i < 4; i++) { m_r[i] = -INFINITY; l_r[i] = 0.f; }
#pragma unroll
    for (int ip = 0; ip < 2; ip++)
#pragma unroll
        for (int j = 0; j < 4; j++) o2[ip][j] = 0ULL;

    for (int jt = 0; jt <= qt; jt++) {
        const int kv0 = jt * 64;
        __syncthreads();
#pragma unroll
        for (int ch = 0; ch < 4; ch++) {
            int idx = tid + ch * 256;
            int row = idx >> 4;
            int cq  = idx & 15;
            float4 kv = *(const float4*)(g_kT + (size_t)(b * ND + row) * NT + kv0 + cq * 4);
            *(float4*)&kp_s[ksw(row, cq)] = kv;
            float4 vv = *(const float4*)(g_v + (size_t)(b * NT + kv0 + row) * ND + cq * 4);
            *(float4*)&v_s[row * 64 + cq * 4] = vv;
        }
        __syncthreads();

        ull s2[2][4];
#pragma unroll
        for (int ip = 0; ip < 2; ip++)
#pragma unroll
            for (int j = 0; j < 4; j++) s2[ip][j] = 0ULL;

#pragma unroll 8
        for (int d = 0; d < 64; d++) {
            float4 qv = *(const float4*)&q_s[d * 64 + r0];
            float4 kv = *(const float4*)&kp_s[ksw(d, tx)];
            ull qp[2] = {pack2(qv.x, qv.y), pack2(qv.z, qv.w)};
            ull kb[4] = {bcast2(kv.x), bcast2(kv.y), bcast2(kv.z), bcast2(kv.w)};
#pragma unroll
            for (int ip = 0; ip < 2; ip++)
#pragma unroll
                for (int j = 0; j < 4; j++)
                    fma2(s2[ip][j], qp[ip], kb[j]);
        }

        float s[4][4];
#pragma unroll
        for (int ip = 0; ip < 2; ip++)
#pragma unroll
            for (int j = 0; j < 4; j++) {
                float2 tt = unpk(s2[ip][j]);
                s[2 * ip][j]     = tt.x;
                s[2 * ip + 1][j] = tt.y;
            }

        if (jt == qt) {
#pragma unroll
            for (int i = 0; i < 4; i++)
#pragma unroll
                for (int j = 0; j < 4; j++)
                    if (c0 + j > r0 + i) s[i][j] = -INFINITY;
        }

        float p[4][4], alpha[4];
#pragma unroll
        for (int i = 0; i < 4; i++) {
            float mx = fmaxf(fmaxf(s[i][0], s[i][1]), fmaxf(s[i][2], s[i][3]));
#pragma unroll
            for (int w = 8; w >= 1; w >>= 1)
                mx = fmaxf(mx, __shfl_xor_sync(0xffffffffu, mx, w));
            float mn = fmaxf(m_r[i], mx);
            alpha[i] = __expf(m_r[i] - mn);
            m_r[i] = mn;
            float sum = 0.f;
#pragma unroll
            for (int j = 0; j < 4; j++) {
                p[i][j] = __expf(s[i][j] - mn);
                sum += p[i][j];
            }
#pragma unroll
            for (int w = 8; w >= 1; w >>= 1)
                sum += __shfl_xor_sync(0xffffffffu, sum, w);
            l_r[i] = l_r[i] * alpha[i] + sum;
        }
#pragma unroll
        for (int ip = 0; ip < 2; ip++) {
            ull al = pack2(alpha[2 * ip], alpha[2 * ip + 1]);
#pragma unroll
            for (int j = 0; j < 4; j++) mul2(o2[ip][j], o2[ip][j], al);
        }

        __syncthreads();
#pragma unroll
        for (int j = 0; j < 4; j++)
#pragma unroll
            for (int i = 0; i < 4; i++)
                kp_s[ksw(c0 + j, ty) + i] = p[i][j];
        __syncthreads();

#pragma unroll 8
        for (int ss = 0; ss < 64; ss++) {
            float4 pv = *(const float4*)&kp_s[ksw(ss, ty)];
            float4 vv = *(const float4*)&v_s[ss * 64 + c0];
            ull pp[2] = {pack2(pv.x, pv.y), pack2(pv.z, pv.w)};
            ull vb[4] = {bcast2(vv.x), bcast2(vv.y), bcast2(vv.z), bcast2(vv.w)};
#pragma unroll
            for (int ip = 0; ip < 2; ip++)
#pragma unroll
                for (int j = 0; j < 4; j++)
                    fma2(o2[ip][j], pp[ip], vb[j]);
        }
    }

#pragma unroll
    for (int ip = 0; ip < 2; ip++) {
        float inv0 = 1.f / l_r[2 * ip];
        float inv1 = 1.f / l_r[2 * ip + 1];
        float2 t0 = unpk(o2[ip][0]);
        float2 t1 = unpk(o2[ip][1]);
        float2 t2 = unpk(o2[ip][2]);
        float2 t3 = unpk(o2[ip][3]);
        float4 ov0 = make_float4(t0.x * inv0, t1.x * inv0, t2.x * inv0, t3.x * inv0);
        float4 ov1 = make_float4(t0.y * inv1, t1.y * inv1, t2.y * inv1, t3.y * inv1);
        *(float4*)(out + (size_t)(b * NT + q0 + r0 + 2 * ip) * ND + c0)     = ov0;
        *(float4*)(out + (size_t)(b * NT + q0 + r0 + 2 * ip + 1) * ND + c0) = ov1;
    }
}

extern "C" void kernel_launch(void* const* d_in, const int* in_sizes, int n_in,
                              void* d_out, int out_size) {
    (void)in_sizes; (void)n_in; (void)out_size;
    const float* x  = (const float*)d_in[0];
    const float* Wq = (const float*)d_in[1];
    const float* Wk = (const float*)d_in[2];
    const float* Wv = (const float*)d_in[3];
    float* out = (float*)d_out;

    wconv_kernel<<<576, 256>>>(Wq, Wk, Wv);
    qkv_mma<<<768, 256>>>(x);
    attn_kernel<<<dim3(16, 32), 256>>>(out);
}

// round 5
// speedup vs baseline: 1.9489x; 1.3891x over previous
#include <cuda_runtime.h>
#include <cuda_bf16.h>
#include <math.h>
#include <cstdint>

#define NB 32
#define NT 1024
#define NC 768
#define ND 64

// pack two f32 -> bf16x2 (first arg = low half)
__device__ __forceinline__ uint32_t pack_bf2(float lo, float hi) {
    uint32_t r; asm("cvt.rn.bf16x2.f32 %0, %1, %2;" : "=r"(r) : "f"(hi), "f"(lo)); return r;
}
__device__ __forceinline__ float lo_bf(uint32_t h) { return __uint_as_float(h << 16); }
__device__ __forceinline__ float hi_bf(uint32_t h) { return __uint_as_float(h & 0xffff0000u); }

// HMMA m16n8k16 bf16, fp32 accum (portable, sm_80+)
__device__ __forceinline__ void mma16816(float* c, const uint32_t* a, const uint32_t* b) {
    asm volatile(
        "mma.sync.aligned.m16n8k16.row.col.f32.bf16.bf16.f32 "
        "{%0,%1,%2,%3}, {%4,%5,%6,%7}, {%8,%9}, {%0,%1,%2,%3};"
        : "+f"(c[0]), "+f"(c[1]), "+f"(c[2]), "+f"(c[3])
        : "r"(a[0]), "r"(a[1]), "r"(a[2]), "r"(a[3]), "r"(b[0]), "r"(b[1]));
}

// ---- global scratch: bf16 hi/lo, 16B-chunk XOR swizzle by (row & 7) ----
// q,k: [b*1024+t][64 d], row = t (128 B). v: transposed [b*64+d][1024 t], row = d.
__device__ __align__(16) __nv_bfloat16 g_qh[NB * NT * ND];
__device__ __align__(16) __nv_bfloat16 g_ql[NB * NT * ND];
__device__ __align__(16) __nv_bfloat16 g_kh[NB * NT * ND];
__device__ __align__(16) __nv_bfloat16 g_kl[NB * NT * ND];
__device__ __align__(16) __nv_bfloat16 g_vth[NB * ND * NT];
__device__ __align__(16) __nv_bfloat16 g_vtl[NB * ND * NT];
// W^T in bf16 hi/lo: [mat][n=64][k=768] row-major
__device__ __align__(16) __nv_bfloat16 g_Bh[3 * 64 * NC];
__device__ __align__(16) __nv_bfloat16 g_Bl[3 * 64 * NC];

// ---------------------------------------------------------------------------
// W conversion: fp32 [768][64] -> bf16 hi/lo W^T [mat][64][768]
// ---------------------------------------------------------------------------
__global__ __launch_bounds__(256) void wconv_kernel(
    const float* __restrict__ Wq, const float* __restrict__ Wk, const float* __restrict__ Wv)
{
    int idx = blockIdx.x * 256 + threadIdx.x;
    int mat = idx / 49152;
    int r = idx - mat * 49152;
    int n = r / NC;
    int k = r - n * NC;
    const float* W = (mat == 0) ? Wq : (mat == 1) ? Wk : Wv;
    float v = W[k * ND + n];
    __nv_bfloat16 h = __float2bfloat16(v);
    __nv_bfloat16 l = __float2bfloat16(v - __bfloat162float(h));
    g_Bh[idx] = h;
    g_Bl[idx] = l;
}

// ---------------------------------------------------------------------------
// QKV GEMM via mma.sync bf16-split. grid 768 (bid = mtile*3 + mat), 256 thr.
// Epilogue: RoPE (+scale for q), split to bf16 hi/lo, swizzled global stores.
// ---------------------------------------------------------------------------
#define OFF_AH 0
#define OFF_AL 10240
#define OFF_BH 20480
#define OFF_BL 25600

__global__ __launch_bounds__(256) void qkv_mma(const float* __restrict__ x)
{
    __shared__ __align__(16) char sm[33792];

    const int tid = threadIdx.x;
    const int lane = tid & 31, w = tid >> 5;
    const int warpM = w & 3, warpN = w >> 2;
    const int g = lane >> 2, qd = lane & 3;
    const int bid = blockIdx.x;
    const int mat = bid % 3;
    const int m0 = (bid / 3) * 128;

    float acc[2][4][4];
#pragma unroll
    for (int mt = 0; mt < 2; mt++)
#pragma unroll
        for (int nt = 0; nt < 4; nt++)
#pragma unroll
            for (int i = 0; i < 4; i++) acc[mt][nt][i] = 0.f;

    const int am = tid >> 1, kh = tid & 1;
    const float* xrow = x + (size_t)(m0 + am) * NC + kh * 16;
    const int brow = tid >> 2, bq = tid & 3;
    const __nv_bfloat16* bsrcH = g_Bh + mat * 49152 + brow * NC;
    const __nv_bfloat16* bsrcL = g_Bl + mat * 49152 + brow * NC;

    for (int c = 0; c < 24; c++) {
        __syncthreads();
#pragma unroll
        for (int gg = 0; gg < 2; gg++) {
            float4 a = *(const float4*)(xrow + c * 32 + gg * 8);
            float4 b = *(const float4*)(xrow + c * 32 + gg * 8 + 4);
            uint32_t h0 = pack_bf2(a.x, a.y);
            uint32_t h1 = pack_bf2(a.z, a.w);
            uint32_t h2 = pack_bf2(b.x, b.y);
            uint32_t h3 = pack_bf2(b.z, b.w);
            uint32_t l0 = pack_bf2(a.x - lo_bf(h0), a.y - hi_bf(h0));
            uint32_t l1 = pack_bf2(a.z - lo_bf(h1), a.w - hi_bf(h1));
            uint32_t l2 = pack_bf2(b.x - lo_bf(h2), b.y - hi_bf(h2));
            uint32_t l3 = pack_bf2(b.z - lo_bf(h3), b.w - hi_bf(h3));
            int off = am * 80 + kh * 32 + gg * 16;
            *(uint4*)(sm + OFF_AH + off) = make_uint4(h0, h1, h2, h3);
            *(uint4*)(sm + OFF_AL + off) = make_uint4(l0, l1, l2, l3);
        }
        {
            int off = brow * 80 + bq * 16;
            *(uint4*)(sm + OFF_BH + off) = *(const uint4*)(bsrcH + c * 32 + bq * 8);
            *(uint4*)(sm + OFF_BL + off) = *(const uint4*)(bsrcL + c * 32 + bq * 8);
        }
        __syncthreads();

#pragma unroll
        for (int ks = 0; ks < 2; ks++) {
            const int kb = ks * 32 + qd * 4;
            uint32_t ah[2][4], al[2][4];
#pragma unroll
            for (int mt = 0; mt < 2; mt++) {
                int r = warpM * 32 + mt * 16 + g;
                int o0 = r * 80 + kb;
                int o1 = o0 + 8 * 80;
                ah[mt][0] = *(const uint32_t*)(sm + OFF_AH + o0);
                ah[mt][1] = *(const uint32_t*)(sm + OFF_AH + o1);
                ah[mt][2] = *(const uint32_t*)(sm + OFF_AH + o0 + 16);
                ah[mt][3] = *(const uint32_t*)(sm + OFF_AH + o1 + 16);
                al[mt][0] = *(const uint32_t*)(sm + OFF_AL + o0);
                al[mt][1] = *(const uint32_t*)(sm + OFF_AL + o1);
                al[mt][2] = *(const uint32_t*)(sm + OFF_AL + o0 + 16);
                al[mt][3] = *(const uint32_t*)(sm + OFF_AL + o1 + 16);
            }
#pragma unroll
            for (int nt = 0; nt < 4; nt++) {
                int n = warpN * 32 + nt * 8 + g;
                int ob = n * 80 + kb;
                uint32_t bh[2] = {*(const uint32_t*)(sm + OFF_BH + ob),
                                  *(const uint32_t*)(sm + OFF_BH + ob + 16)};
                uint32_t bl[2] = {*(const uint32_t*)(sm + OFF_BL + ob),
                                  *(const uint32_t*)(sm + OFF_BL + ob + 16)};
#pragma unroll
                for (int mt = 0; mt < 2; mt++) {
                    mma16816(acc[mt][nt], ah[mt], bh);
                    mma16816(acc[mt][nt], ah[mt], bl);
                    mma16816(acc[mt][nt], al[mt], bh);
                }
            }
        }
    }
    __syncthreads();

    if (mat < 2) {
        // RoPE + (scale for q) + split, direct swizzled stores (natural [t][d])
        const float sc = (mat == 0) ? 0.03608439182435161f : 1.0f;  // 768^-0.5
        __nv_bfloat16* dstH = (mat == 0) ? g_qh : g_kh;
        __nv_bfloat16* dstL = (mat == 0) ? g_ql : g_kl;
#pragma unroll
        for (int nt = 0; nt < 4; nt++) {
            int c0 = warpN * 32 + nt * 8 + qd * 2;
            int pi = c0 >> 1;
            float freq = expf((float)(2 * pi) * (-9.210340371976184f / (float)ND));
            int chunk = c0 >> 3;
            int bw = (c0 & 7) * 2;
#pragma unroll
            for (int mt = 0; mt < 2; mt++) {
#pragma unroll
                for (int half = 0; half < 2; half++) {
                    int ml = warpM * 32 + mt * 16 + g + half * 8;
                    int r = m0 + ml;
                    float sv, cv;
                    sincosf((float)(r & (NT - 1)) * freq, &sv, &cv);
                    float e = acc[mt][nt][half * 2], o = acc[mt][nt][half * 2 + 1];
                    float re = (e * cv - o * sv) * sc;
                    float ro = (e * sv + o * cv) * sc;
                    uint32_t h = pack_bf2(re, ro);
                    uint32_t l = pack_bf2(re - lo_bf(h), ro - hi_bf(h));
                    size_t byte = (size_t)r * 128 + 16 * (chunk ^ (ml & 7)) + bw;
                    *(uint32_t*)((char*)dstH + byte) = h;
                    *(uint32_t*)((char*)dstL + byte) = l;
                }
            }
        }
    } else {
        // v: transpose via smem to [d][t], split, swizzled stores
        float* vsm = (float*)sm;   // [64][132]
#pragma unroll
        for (int nt = 0; nt < 4; nt++) {
            int c0 = warpN * 32 + nt * 8 + qd * 2;
#pragma unroll
            for (int mt = 0; mt < 2; mt++) {
#pragma unroll
                for (int half = 0; half < 2; half++) {
                    int ml = warpM * 32 + mt * 16 + g + half * 8;
                    vsm[c0 * 132 + ml]       = acc[mt][nt][half * 2];
                    vsm[(c0 + 1) * 132 + ml] = acc[mt][nt][half * 2 + 1];
                }
            }
        }
        __syncthreads();
        const int bb = m0 >> 10;
        const int t0l = m0 & (NT - 1);
#pragma unroll
        for (int i = 0; i < 16; i++) {
            int idx = tid + i * 256;        // 4096 units
            int d = idx >> 6;
            int sl = (idx & 63) * 2;
            float v0 = vsm[d * 132 + sl];
            float v1 = vsm[d * 132 + sl + 1];
            uint32_t h = pack_bf2(v0, v1);
            uint32_t l = pack_bf2(v0 - lo_bf(h), v1 - hi_bf(h));
            int t = t0l + sl;
            size_t byte = ((size_t)((bb * 64 + d) * 1024) + (t & ~63)) * 2
                        + 16 * ((((t & 63) >> 3)) ^ (d & 7)) + (t & 7) * 2;
            *(uint32_t*)((char*)g_vth + byte) = h;
            *(uint32_t*)((char*)g_vtl + byte) = l;
        }
    }
}

// ---------------------------------------------------------------------------
// Tensorized flash attention. grid (16, 32), 128 threads (4 warps).
// Warp owns 16 q-rows x full 64 N. P reuses S accumulators as A fragments.
// smem 48 KB static: Q/K/V bf16 hi+lo tiles, swizzle baked into global layout.
// ---------------------------------------------------------------------------
#define AQH 0
#define AQL 8192
#define AKH 16384
#define AKL 24576
#define AVH 32768
#define AVL 40960

__global__ __launch_bounds__(128, 4) void attn_mma(float* __restrict__ out)
{
    __shared__ __align__(16) char sm[49152];

    const int tid = threadIdx.x;
    const int lane = tid & 31, w = tid >> 5;
    const int g = lane >> 2, qd = lane & 3;
    const int b = blockIdx.y;
    const int qt = 15 - (int)blockIdx.x;      // heavy tiles first
    const int q0 = qt * 64;

    // load Q tiles (hi/lo): straight copies, swizzle pre-applied
    {
        const uint4* srcH = (const uint4*)(g_qh + (size_t)(b * NT + q0) * ND);
        const uint4* srcL = (const uint4*)(g_ql + (size_t)(b * NT + q0) * ND);
#pragma unroll
        for (int i = 0; i < 4; i++) {
            ((uint4*)(sm + AQH))[tid + i * 128] = srcH[tid + i * 128];
            ((uint4*)(sm + AQL))[tid + i * 128] = srcL[tid + i * 128];
        }
    }

    float o[8][4];
    float m_r[2], l_r[2];
#pragma unroll
    for (int nd = 0; nd < 8; nd++)
#pragma unroll
        for (int i = 0; i < 4; i++) o[nd][i] = 0.f;
    m_r[0] = m_r[1] = -INFINITY;
    l_r[0] = l_r[1] = 0.f;

    const int arow = w * 16 + g;
    const int abase = arow * 128 + qd * 4;
    const int ax = arow & 7;     // == g

    for (int jt = 0; jt <= qt; jt++) {
        const int kv0 = jt * 64;
        __syncthreads();
        // load K (contiguous) and V (row-strided) hi/lo tiles
        {
            const uint4* kH = (const uint4*)(g_kh + (size_t)(b * NT + kv0) * ND);
            const uint4* kL = (const uint4*)(g_kl + (size_t)(b * NT + kv0) * ND);
#pragma unroll
            for (int i = 0; i < 4; i++) {
                ((uint4*)(sm + AKH))[tid + i * 128] = kH[tid + i * 128];
                ((uint4*)(sm + AKL))[tid + i * 128] = kL[tid + i * 128];
            }
#pragma unroll
            for (int i = 0; i < 4; i++) {
                int idx = tid + i * 128;      // 512 units
                int d = idx >> 3, c = idx & 7;
                size_t src = ((size_t)(b * 64 + d) * 1024 + kv0) + c * 8;
                ((uint4*)(sm + AVH))[idx] = *(const uint4*)(g_vth + src);
                ((uint4*)(sm + AVL))[idx] = *(const uint4*)(g_vtl + src);
            }
        }
        __syncthreads();

        // ---- S = Q @ K^T (bf16 split) ----
        float s[8][4];
#pragma unroll
        for (int nt = 0; nt < 8; nt++)
#pragma unroll
            for (int i = 0; i < 4; i++) s[nt][i] = 0.f;

#pragma unroll
        for (int ks = 0; ks < 4; ks++) {
            uint32_t ah[4], al[4];
            int cA = 16 * ((2 * ks) ^ ax), cB = 16 * ((2 * ks + 1) ^ ax);
            ah[0] = *(const uint32_t*)(sm + AQH + abase + cA);
            ah[1] = *(const uint32_t*)(sm + AQH + abase + 1024 + cA);
            ah[2] = *(const uint32_t*)(sm + AQH + abase + cB);
            ah[3] = *(const uint32_t*)(sm + AQH + abase + 1024 + cB);
            al[0] = *(const uint32_t*)(sm + AQL + abase + cA);
            al[1] = *(const uint32_t*)(sm + AQL + abase + 1024 + cA);
            al[2] = *(const uint32_t*)(sm + AQL + abase + cB);
            al[3] = *(const uint32_t*)(sm + AQL + abase + 1024 + cB);
#pragma unroll
            for (int nt = 0; nt < 8; nt++) {
                int brow = nt * 8 + g;
                int bbase = brow * 128 + qd * 4;
                int c0 = 16 * ((2 * ks) ^ g), c1 = 16 * ((2 * ks + 1) ^ g);
                uint32_t bh[2] = {*(const uint32_t*)(sm + AKH + bbase + c0),
                                  *(const uint32_t*)(sm + AKH + bbase + c1)};
                uint32_t bl[2] = {*(const uint32_t*)(sm + AKL + bbase + c0),
                                  *(const uint32_t*)(sm + AKL + bbase + c1)};
                mma16816(s[nt], ah, bh);
                mma16816(s[nt], ah, bl);
                mma16816(s[nt], al, bh);
            }
        }

        // causal mask (diagonal tile only)
        if (jt == qt) {
#pragma unroll
            for (int nt = 0; nt < 8; nt++) {
                int col = q0 + nt * 8 + qd * 2;
#pragma unroll
                for (int half = 0; half < 2; half++) {
                    int row = q0 + w * 16 + g + half * 8;
                    if (col > row)     s[nt][half * 2]     = -INFINITY;
                    if (col + 1 > row) s[nt][half * 2 + 1] = -INFINITY;
                }
            }
        }

        // ---- online softmax (quad-local reductions) ----
#pragma unroll
        for (int half = 0; half < 2; half++) {
            float mx = -INFINITY;
#pragma unroll
            for (int nt = 0; nt < 8; nt++)
                mx = fmaxf(mx, fmaxf(s[nt][half * 2], s[nt][half * 2 + 1]));
            mx = fmaxf(mx, __shfl_xor_sync(0xffffffffu, mx, 1));
            mx = fmaxf(mx, __shfl_xor_sync(0xffffffffu, mx, 2));
            float mn = fmaxf(m_r[half], mx);
            float alpha = __expf(m_r[half] - mn);
            m_r[half] = mn;
            float sum = 0.f;
#pragma unroll
            for (int nt = 0; nt < 8; nt++) {
                float p0 = __expf(s[nt][half * 2] - mn);
                float p1 = __expf(s[nt][half * 2 + 1] - mn);
                s[nt][half * 2] = p0;
                s[nt][half * 2 + 1] = p1;
                sum += p0 + p1;
            }
            sum += __shfl_xor_sync(0xffffffffu, sum, 1);
            sum += __shfl_xor_sync(0xffffffffu, sum, 2);
            l_r[half] = l_r[half] * alpha + sum;
#pragma unroll
            for (int nd = 0; nd < 8; nd++) {
                o[nd][half * 2] *= alpha;
                o[nd][half * 2 + 1] *= alpha;
            }
        }

        // ---- O += P @ V (P from regs, bf16 split) ----
#pragma unroll
        for (int ks = 0; ks < 4; ks++) {
            uint32_t ah[4], al[4];
            ah[0] = pack_bf2(s[2 * ks][0], s[2 * ks][1]);
            ah[1] = pack_bf2(s[2 * ks][2], s[2 * ks][3]);
            ah[2] = pack_bf2(s[2 * ks + 1][0], s[2 * ks + 1][1]);
            ah[3] = pack_bf2(s[2 * ks + 1][2], s[2 * ks + 1][3]);
            al[0] = pack_bf2(s[2 * ks][0] - lo_bf(ah[0]), s[2 * ks][1] - hi_bf(ah[0]));
            al[1] = pack_bf2(s[2 * ks][2] - lo_bf(ah[1]), s[2 * ks][3] - hi_bf(ah[1]));
            al[2] = pack_bf2(s[2 * ks + 1][0] - lo_bf(ah[2]), s[2 * ks + 1][1] - hi_bf(ah[2]));
            al[3] = pack_bf2(s[2 * ks + 1][2] - lo_bf(ah[3]), s[2 * ks + 1][3] - hi_bf(ah[3]));
#pragma unroll
            for (int nd = 0; nd < 8; nd++) {
                int brow = nd * 8 + g;
                int bbase = brow * 128 + qd * 4;
                int c0 = 16 * ((2 * ks) ^ g), c1 = 16 * ((2 * ks + 1) ^ g);
                uint32_t bh[2] = {*(const uint32_t*)(sm + AVH + bbase + c0),
                                  *(const uint32_t*)(sm + AVH + bbase + c1)};
                uint32_t bl[2] = {*(const uint32_t*)(sm + AVL + bbase + c0),
                                  *(const uint32_t*)(sm + AVL + bbase + c1)};
                mma16816(o[nd], ah, bh);
                mma16816(o[nd], ah, bl);
                mma16816(o[nd], al, bh);
            }
        }
    }

    // epilogue: normalize + store (natural [b][t][d])
    float inv0 = 1.f / l_r[0];
    float inv1 = 1.f / l_r[1];
    int row0 = b * NT + q0 + w * 16 + g;
#pragma unroll
    for (int nd = 0; nd < 8; nd++) {
        int d = nd * 8 + qd * 2;
        *(float2*)(out + (size_t)row0 * ND + d) =
            make_float2(o[nd][0] * inv0, o[nd][1] * inv0);
        *(float2*)(out + (size_t)(row0 + 8) * ND + d) =
            make_float2(o[nd][2] * inv1, o[nd][3] * inv1);
    }
}

extern "C" void kernel_launch(void* const* d_in, const int* in_sizes, int n_in,
                              void* d_out, int out_size) {
    (void)in_sizes; (void)n_in; (void)out_size;
    const float* x  = (const float*)d_in[0];
    const float* Wq = (const float*)d_in[1];
    const float* Wk = (const float*)d_in[2];
    const float* Wv = (const float*)d_in[3];
    float* out = (float*)d_out;

    wconv_kernel<<<576, 256>>>(Wq, Wk, Wv);
    qkv_mma<<<768, 256>>>(x);
    attn_mma<<<dim3(16, 32), 128>>>(out);
}

// round 6
// speedup vs baseline: 2.6015x; 1.3349x over previous
#include <cuda_runtime.h>
#include <cuda_bf16.h>
#include <math.h>
#include <cstdint>

#define NB 32
#define NT 1024
#define NC 768
#define ND 64

// ---- helpers ----
__device__ __forceinline__ uint32_t pack_bf2(float lo, float hi) {
    uint32_t r; asm("cvt.rn.bf16x2.f32 %0, %1, %2;" : "=r"(r) : "f"(hi), "f"(lo)); return r;
}
__device__ __forceinline__ float lo_bf(uint32_t h) { return __uint_as_float(h << 16); }
__device__ __forceinline__ float hi_bf(uint32_t h) { return __uint_as_float(h & 0xffff0000u); }

__device__ __forceinline__ void mma16816(float* c, const uint32_t* a, const uint32_t* b) {
    asm volatile(
        "mma.sync.aligned.m16n8k16.row.col.f32.bf16.bf16.f32 "
        "{%0,%1,%2,%3}, {%4,%5,%6,%7}, {%8,%9}, {%0,%1,%2,%3};"
        : "+f"(c[0]), "+f"(c[1]), "+f"(c[2]), "+f"(c[3])
        : "r"(a[0]), "r"(a[1]), "r"(a[2]), "r"(a[3]), "r"(b[0]), "r"(b[1]));
}
#define LDM4(r, addr) \
    asm volatile("ldmatrix.sync.aligned.m8n8.x4.shared.b16 {%0,%1,%2,%3}, [%4];" \
        : "=r"((r)[0]), "=r"((r)[1]), "=r"((r)[2]), "=r"((r)[3]) : "r"(addr))
#define CP16(dst, src) \
    asm volatile("cp.async.cg.shared.global [%0], [%1], 16;" :: "r"(dst), "l"(src))
#define CP_COMMIT() asm volatile("cp.async.commit_group;" ::: "memory")
#define CP_WAIT0()  asm volatile("cp.async.wait_group 0;" ::: "memory")

__device__ __forceinline__ uint32_t smem_u32(const void* p) {
    return (uint32_t)__cvta_generic_to_shared(p);
}

// ---- global scratch: bf16 hi/lo, 16B-chunk XOR swizzle by (row & 7) ----
__device__ __align__(16) __nv_bfloat16 g_qh[NB * NT * ND];
__device__ __align__(16) __nv_bfloat16 g_ql[NB * NT * ND];
__device__ __align__(16) __nv_bfloat16 g_kh[NB * NT * ND];
__device__ __align__(16) __nv_bfloat16 g_kl[NB * NT * ND];
__device__ __align__(16) __nv_bfloat16 g_vth[NB * ND * NT];
__device__ __align__(16) __nv_bfloat16 g_vtl[NB * ND * NT];
__device__ __align__(16) __nv_bfloat16 g_Bh[3 * 64 * NC];
__device__ __align__(16) __nv_bfloat16 g_Bl[3 * 64 * NC];

// ---------------------------------------------------------------------------
// W conversion
// ---------------------------------------------------------------------------
__global__ __launch_bounds__(256) void wconv_kernel(
    const float* __restrict__ Wq, const float* __restrict__ Wk, const float* __restrict__ Wv)
{
    int idx = blockIdx.x * 256 + threadIdx.x;
    int mat = idx / 49152;
    int r = idx - mat * 49152;
    int n = r / NC;
    int k = r - n * NC;
    const float* W = (mat == 0) ? Wq : (mat == 1) ? Wk : Wv;
    float v = W[k * ND + n];
    __nv_bfloat16 h = __float2bfloat16(v);
    __nv_bfloat16 l = __float2bfloat16(v - __bfloat162float(h));
    g_Bh[idx] = h;
    g_Bl[idx] = l;
}

// ---------------------------------------------------------------------------
// QKV GEMM: 2-stage cp.async pipeline + ldmatrix + bf16-split HMMA.
// grid 768 (bid = mtile*3 + mat), 256 threads, 61440 B dynamic smem.
// Stage layout (30720 B): AH 0 (128x80), AL 10240, BH 20480 (64x80), BL 25600.
// ---------------------------------------------------------------------------
#define QS_AH 0
#define QS_AL 10240
#define QS_BH 20480
#define QS_BL 25600
#define QS_STAGE 30720
#define QKV_SMEM 61440

__global__ __launch_bounds__(256) void qkv_mma(const float* __restrict__ x)
{
    extern __shared__ __align__(16) char sm[];
    const uint32_t smb = smem_u32(sm);

    const int tid = threadIdx.x;
    const int lane = tid & 31, w = tid >> 5;
    const int warpM = w & 3, warpN = w >> 2;
    const int g = lane >> 2, qd = lane & 3;
    const int bid = blockIdx.x;
    const int mat = bid % 3;
    const int m0 = (bid / 3) * 128;

    float acc[2][4][4];
#pragma unroll
    for (int mt = 0; mt < 2; mt++)
#pragma unroll
        for (int nt = 0; nt < 4; nt++)
#pragma unroll
            for (int i = 0; i < 4; i++) acc[mt][nt][i] = 0.f;

    const int am = tid >> 1, kh = tid & 1;
    const float* xrow = x + (size_t)(m0 + am) * NC + kh * 16;
    // B cp.async mapping: chunk = tid -> n = tid>>2, q = tid&3
    const int bn = tid >> 2, bq = tid & 3;
    const char* bgH = (const char*)(g_Bh + mat * 49152 + bn * NC) + bq * 16;
    const char* bgL = (const char*)(g_Bl + mat * 49152 + bn * NC) + bq * 16;
    const uint32_t bsoff = bn * 80 + bq * 16;
    const uint32_t asoff = am * 80 + kh * 32;

    // fragment load offsets (pitch 80, no XOR)
    const uint32_t aoff = (uint32_t)((warpM * 32 + (lane & 15)) * 80 + ((lane >> 4) << 4));
    const uint32_t boff = (uint32_t)((warpN * 32 + (lane & 7) + ((lane >> 4) << 3)) * 80
                                     + (((lane >> 3) & 1) << 4));

    // prologue: A(0) -> regs, B(0) -> stage 0
    float4 rA[2][4];
#pragma unroll
    for (int j = 0; j < 4; j++) rA[0][j] = *(const float4*)(xrow + j * 4);
    CP16(smb + QS_BH + bsoff, bgH);
    CP16(smb + QS_BL + bsoff, bgL);
    CP_COMMIT();

#pragma unroll 2
    for (int c = 0; c < 24; c++) {
        const int s = c & 1;
        const uint32_t stb = smb + s * QS_STAGE;

        // prefetch A(c+1) into other reg buffer
        if (c + 1 < 24) {
#pragma unroll
            for (int j = 0; j < 4; j++)
                rA[(c + 1) & 1][j] = *(const float4*)(xrow + (c + 1) * 32 + j * 4);
        }
        // convert A(c) -> STS stage s
        {
            uint32_t h[8], l[8];
#pragma unroll
            for (int j = 0; j < 4; j++) {
                float4 f = rA[c & 1][j];
                uint32_t hh0 = pack_bf2(f.x, f.y);
                uint32_t hh1 = pack_bf2(f.z, f.w);
                h[2 * j] = hh0; h[2 * j + 1] = hh1;
                l[2 * j]     = pack_bf2(f.x - lo_bf(hh0), f.y - hi_bf(hh0));
                l[2 * j + 1] = pack_bf2(f.z - lo_bf(hh1), f.w - hi_bf(hh1));
            }
            char* base = sm + s * QS_STAGE;
            *(uint4*)(base + QS_AH + asoff)      = make_uint4(h[0], h[1], h[2], h[3]);
            *(uint4*)(base + QS_AH + asoff + 16) = make_uint4(h[4], h[5], h[6], h[7]);
            *(uint4*)(base + QS_AL + asoff)      = make_uint4(l[0], l[1], l[2], l[3]);
            *(uint4*)(base + QS_AL + asoff + 16) = make_uint4(l[4], l[5], l[6], l[7]);
        }

        CP_WAIT0();          // B(c) arrived
        __syncthreads();     // all STS visible; prev MMA done

        if (c + 1 < 24) {    // B(c+1) -> other stage, overlaps MMA below
            const uint32_t nst = smb + (s ^ 1) * QS_STAGE;
            CP16(nst + QS_BH + bsoff, bgH + (c + 1) * 64);
            CP16(nst + QS_BL + bsoff, bgL + (c + 1) * 64);
            CP_COMMIT();
        }

        // ---- MMA on stage s ----
#pragma unroll
        for (int ks = 0; ks < 2; ks++) {
            uint32_t ah[2][4], al[2][4];
#pragma unroll
            for (int mt = 0; mt < 2; mt++) {
                uint32_t a = stb + QS_AH + aoff + mt * (16 * 80) + ks * 32;
                LDM4(ah[mt], a);
                LDM4(al[mt], a + (QS_AL - QS_AH));
            }
#pragma unroll
            for (int ntp = 0; ntp < 2; ntp++) {
                uint32_t bh4[4], bl4[4];
                uint32_t ba = stb + QS_BH + boff + ntp * (16 * 80) + ks * 32;
                LDM4(bh4, ba);
                LDM4(bl4, ba + (QS_BL - QS_BH));
#pragma unroll
                for (int mt = 0; mt < 2; mt++) {
                    mma16816(acc[mt][2 * ntp], ah[mt], bh4);
                    mma16816(acc[mt][2 * ntp], ah[mt], bl4);
                    mma16816(acc[mt][2 * ntp], al[mt], bh4);
                    mma16816(acc[mt][2 * ntp + 1], ah[mt], bh4 + 2);
                    mma16816(acc[mt][2 * ntp + 1], ah[mt], bl4 + 2);
                    mma16816(acc[mt][2 * ntp + 1], al[mt], bh4 + 2);
                }
            }
        }
    }
    __syncthreads();

    if (mat < 2) {
        const float sc = (mat == 0) ? 0.03608439182435161f : 1.0f;  // 768^-0.5
        __nv_bfloat16* dstH = (mat == 0) ? g_qh : g_kh;
        __nv_bfloat16* dstL = (mat == 0) ? g_ql : g_kl;
#pragma unroll
        for (int nt = 0; nt < 4; nt++) {
            int c0 = warpN * 32 + nt * 8 + qd * 2;
            int pi = c0 >> 1;
            float freq = expf((float)(2 * pi) * (-9.210340371976184f / (float)ND));
            int chunk = c0 >> 3;
            int bw = (c0 & 7) * 2;
#pragma unroll
            for (int mt = 0; mt < 2; mt++) {
#pragma unroll
                for (int half = 0; half < 2; half++) {
                    int ml = warpM * 32 + mt * 16 + g + half * 8;
                    int r = m0 + ml;
                    float sv, cv;
                    sincosf((float)(r & (NT - 1)) * freq, &sv, &cv);
                    float e = acc[mt][nt][half * 2], o = acc[mt][nt][half * 2 + 1];
                    float re = (e * cv - o * sv) * sc;
                    float ro = (e * sv + o * cv) * sc;
                    uint32_t h = pack_bf2(re, ro);
                    uint32_t l = pack_bf2(re - lo_bf(h), ro - hi_bf(h));
                    size_t byte = (size_t)r * 128 + 16 * (chunk ^ (ml & 7)) + bw;
                    *(uint32_t*)((char*)dstH + byte) = h;
                    *(uint32_t*)((char*)dstL + byte) = l;
                }
            }
        }
    } else {
        float* vsm = (float*)sm;   // [64][132]
#pragma unroll
        for (int nt = 0; nt < 4; nt++) {
            int c0 = warpN * 32 + nt * 8 + qd * 2;
#pragma unroll
            for (int mt = 0; mt < 2; mt++) {
#pragma unroll
                for (int half = 0; half < 2; half++) {
                    int ml = warpM * 32 + mt * 16 + g + half * 8;
                    vsm[c0 * 132 + ml]       = acc[mt][nt][half * 2];
                    vsm[(c0 + 1) * 132 + ml] = acc[mt][nt][half * 2 + 1];
                }
            }
        }
        __syncthreads();
        const int bb = m0 >> 10;
        const int t0l = m0 & (NT - 1);
#pragma unroll
        for (int i = 0; i < 16; i++) {
            int idx = tid + i * 256;
            int d = idx >> 6;
            int sl = (idx & 63) * 2;
            float v0 = vsm[d * 132 + sl];
            float v1 = vsm[d * 132 + sl + 1];
            uint32_t h = pack_bf2(v0, v1);
            uint32_t l = pack_bf2(v0 - lo_bf(h), v1 - hi_bf(h));
            int t = t0l + sl;
            size_t byte = ((size_t)((bb * 64 + d) * 1024) + (t & ~63)) * 2
                        + 16 * ((((t & 63) >> 3)) ^ (d & 7)) + (t & 7) * 2;
            *(uint32_t*)((char*)g_vth + byte) = h;
            *(uint32_t*)((char*)g_vtl + byte) = l;
        }
    }
}

// ---------------------------------------------------------------------------
// Flash attention: 2-stage cp.async KV pipeline + ldmatrix + bf16-split HMMA.
// grid (16, 32), 128 threads. smem 81920 B dynamic:
//   QH 0, QL 8192, stages at 16384 (32768 each: KH 0, KL 8192, VH 16384, VL 24576)
// ---------------------------------------------------------------------------
#define AS_Q 0
#define AS_QL 8192
#define AS_ST 16384
#define AS_KH 0
#define AS_KL 8192
#define AS_VH 16384
#define AS_VL 24576
#define AS_STAGE 32768
#define ATTN_SMEM 81920

__global__ __launch_bounds__(128) void attn_mma(float* __restrict__ out)
{
    extern __shared__ __align__(16) char sm[];
    const uint32_t smb = smem_u32(sm);

    const int tid = threadIdx.x;
    const int lane = tid & 31, w = tid >> 5;
    const int g = lane >> 2, qd = lane & 3;
    const int b = blockIdx.y;
    const int qt = 15 - (int)blockIdx.x;
    const int q0 = qt * 64;

    // prologue: Q + KV(0) via cp.async, one group
    {
        const char* qH = (const char*)(g_qh + (size_t)(b * NT + q0) * ND);
        const char* qL = (const char*)(g_ql + (size_t)(b * NT + q0) * ND);
#pragma unroll
        for (int i = 0; i < 4; i++) {
            int idx = tid + i * 128;
            CP16(smb + AS_Q + idx * 16, qH + idx * 16);
            CP16(smb + AS_QL + idx * 16, qL + idx * 16);
        }
        const char* kH = (const char*)(g_kh + (size_t)(b * NT + q0 * 0) * ND); // placeholder silence
        (void)kH;
        const char* kHs = (const char*)(g_kh + (size_t)(b * NT + 0) * ND);
        const char* kLs = (const char*)(g_kl + (size_t)(b * NT + 0) * ND);
#pragma unroll
        for (int i = 0; i < 4; i++) {
            int idx = tid + i * 128;
            CP16(smb + AS_ST + AS_KH + idx * 16, kHs + idx * 16);
            CP16(smb + AS_ST + AS_KL + idx * 16, kLs + idx * 16);
            int d = idx >> 3, c = idx & 7;
            const char* vHs = (const char*)(g_vth + (size_t)(b * 64 + d) * 1024) + c * 16;
            const char* vLs = (const char*)(g_vtl + (size_t)(b * 64 + d) * 1024) + c * 16;
            CP16(smb + AS_ST + AS_VH + idx * 16, vHs);
            CP16(smb + AS_ST + AS_VL + idx * 16, vLs);
        }
        CP_COMMIT();
    }
    CP_WAIT0();
    __syncthreads();

    // hoist Q fragments (constant over jt)
    uint32_t qh[4][4], ql[4][4];
    {
        const uint32_t aoffQ = (uint32_t)((w * 16 + (lane & 15)) * 128);
#pragma unroll
        for (int ks = 0; ks < 4; ks++) {
            uint32_t ch = (uint32_t)(((2 * ks + (lane >> 4)) ^ (lane & 7)) * 16);
            LDM4(qh[ks], smb + AS_Q + aoffQ + ch);
            LDM4(ql[ks], smb + AS_QL + aoffQ + ch);
        }
    }

    float o[8][4];
    float m_r[2], l_r[2];
#pragma unroll
    for (int nd = 0; nd < 8; nd++)
#pragma unroll
        for (int i = 0; i < 4; i++) o[nd][i] = 0.f;
    m_r[0] = m_r[1] = -INFINITY;
    l_r[0] = l_r[1] = 0.f;

    const uint32_t browB = (uint32_t)((lane & 7) + ((lane >> 4) << 3));
    const int lx = lane & 7, lb = (lane >> 3) & 1;

    for (int jt = 0; jt <= qt; jt++) {
        const int s = jt & 1;
        const uint32_t stb = smb + AS_ST + s * AS_STAGE;

        if (jt > 0) { CP_WAIT0(); __syncthreads(); }

        if (jt < qt) {   // prefetch KV(jt+1) into other stage
            const int kvn = (jt + 1) * 64;
            const uint32_t nst = smb + AS_ST + (s ^ 1) * AS_STAGE;
            const char* kHs = (const char*)(g_kh + (size_t)(b * NT + kvn) * ND);
            const char* kLs = (const char*)(g_kl + (size_t)(b * NT + kvn) * ND);
#pragma unroll
            for (int i = 0; i < 4; i++) {
                int idx = tid + i * 128;
                CP16(nst + AS_KH + idx * 16, kHs + idx * 16);
                CP16(nst + AS_KL + idx * 16, kLs + idx * 16);
                int d = idx >> 3, c = idx & 7;
                const char* vHs = (const char*)(g_vth + (size_t)((b * 64 + d) * 1024 + kvn)) + c * 16;
                const char* vLs = (const char*)(g_vtl + (size_t)((b * 64 + d) * 1024 + kvn)) + c * 16;
                CP16(nst + AS_VH + idx * 16, vHs);
                CP16(nst + AS_VL + idx * 16, vLs);
            }
            CP_COMMIT();
        }

        // ---- S = Q @ K^T ----
        float s_[8][4];
#pragma unroll
        for (int nt = 0; nt < 8; nt++)
#pragma unroll
            for (int i = 0; i < 4; i++) s_[nt][i] = 0.f;

#pragma unroll
        for (int ks = 0; ks < 4; ks++) {
            uint32_t ch = (uint32_t)(((2 * ks + lb) ^ lx) * 16);
#pragma unroll
            for (int ntp = 0; ntp < 4; ntp++) {
                uint32_t bh4[4], bl4[4];
                uint32_t ba = stb + AS_KH + (ntp * 16 + browB) * 128 + ch;
                LDM4(bh4, ba);
                LDM4(bl4, ba + (AS_KL - AS_KH));
                mma16816(s_[2 * ntp], qh[ks], bh4);
                mma16816(s_[2 * ntp], qh[ks], bl4);
                mma16816(s_[2 * ntp], ql[ks], bh4);
                mma16816(s_[2 * ntp + 1], qh[ks], bh4 + 2);
                mma16816(s_[2 * ntp + 1], qh[ks], bl4 + 2);
                mma16816(s_[2 * ntp + 1], ql[ks], bh4 + 2);
            }
        }

        if (jt == qt) {   // causal mask on diagonal tile
#pragma unroll
            for (int nt = 0; nt < 8; nt++) {
                int col = q0 + nt * 8 + qd * 2;
#pragma unroll
                for (int half = 0; half < 2; half++) {
                    int row = q0 + w * 16 + g + half * 8;
                    if (col > row)     s_[nt][half * 2]     = -INFINITY;
                    if (col + 1 > row) s_[nt][half * 2 + 1] = -INFINITY;
                }
            }
        }

        // ---- online softmax ----
#pragma unroll
        for (int half = 0; half < 2; half++) {
            float mx = -INFINITY;
#pragma unroll
            for (int nt = 0; nt < 8; nt++)
                mx = fmaxf(mx, fmaxf(s_[nt][half * 2], s_[nt][half * 2 + 1]));
            mx = fmaxf(mx, __shfl_xor_sync(0xffffffffu, mx, 1));
            mx = fmaxf(mx, __shfl_xor_sync(0xffffffffu, mx, 2));
            float mn = fmaxf(m_r[half], mx);
            float alpha = __expf(m_r[half] - mn);
            m_r[half] = mn;
            float sum = 0.f;
#pragma unroll
            for (int nt = 0; nt < 8; nt++) {
                float p0 = __expf(s_[nt][half * 2] - mn);
                float p1 = __expf(s_[nt][half * 2 + 1] - mn);
                s_[nt][half * 2] = p0;
                s_[nt][half * 2 + 1] = p1;
                sum += p0 + p1;
            }
            sum += __shfl_xor_sync(0xffffffffu, sum, 1);
            sum += __shfl_xor_sync(0xffffffffu, sum, 2);
            l_r[half] = l_r[half] * alpha + sum;
#pragma unroll
            for (int nd = 0; nd < 8; nd++) {
                o[nd][half * 2] *= alpha;
                o[nd][half * 2 + 1] *= alpha;
            }
        }

        // ---- O += P @ V ----
#pragma unroll
        for (int ks = 0; ks < 4; ks++) {
            uint32_t ah[4], al[4];
            ah[0] = pack_bf2(s_[2 * ks][0], s_[2 * ks][1]);
            ah[1] = pack_bf2(s_[2 * ks][2], s_[2 * ks][3]);
            ah[2] = pack_bf2(s_[2 * ks + 1][0], s_[2 * ks + 1][1]);
            ah[3] = pack_bf2(s_[2 * ks + 1][2], s_[2 * ks + 1][3]);
            al[0] = pack_bf2(s_[2 * ks][0] - lo_bf(ah[0]), s_[2 * ks][1] - hi_bf(ah[0]));
            al[1] = pack_bf2(s_[2 * ks][2] - lo_bf(ah[1]), s_[2 * ks][3] - hi_bf(ah[1]));
            al[2] = pack_bf2(s_[2 * ks + 1][0] - lo_bf(ah[2]), s_[2 * ks + 1][1] - hi_bf(ah[2]));
            al[3] = pack_bf2(s_[2 * ks + 1][2] - lo_bf(ah[3]), s_[2 * ks + 1][3] - hi_bf(ah[3]));
            uint32_t ch = (uint32_t)(((2 * ks + lb) ^ lx) * 16);
#pragma unroll
            for (int ntp = 0; ntp < 4; ntp++) {
                uint32_t bh4[4], bl4[4];
                uint32_t ba = stb + AS_VH + (ntp * 16 + browB) * 128 + ch;
                LDM4(bh4, ba);
                LDM4(bl4, ba + (AS_VL - AS_VH));
                mma16816(o[2 * ntp], ah, bh4);
                mma16816(o[2 * ntp], ah, bl4);
                mma16816(o[2 * ntp], al, bh4);
                mma16816(o[2 * ntp + 1], ah, bh4 + 2);
                mma16816(o[2 * ntp + 1], ah, bl4 + 2);
                mma16816(o[2 * ntp + 1], al, bh4 + 2);
            }
        }
    }

    // epilogue
    float inv0 = 1.f / l_r[0];
    float inv1 = 1.f / l_r[1];
    int row0 = b * NT + q0 + w * 16 + g;
#pragma unroll
    for (int nd = 0; nd < 8; nd++) {
        int d = nd * 8 + qd * 2;
        *(float2*)(out + (size_t)row0 * ND + d) =
            make_float2(o[nd][0] * inv0, o[nd][1] * inv0);
        *(float2*)(out + (size_t)(row0 + 8) * ND + d) =
            make_float2(o[nd][2] * inv1, o[nd][3] * inv1);
    }
}

extern "C" void kernel_launch(void* const* d_in, const int* in_sizes, int n_in,
                              void* d_out, int out_size) {
    (void)in_sizes; (void)n_in; (void)out_size;
    const float* x  = (const float*)d_in[0];
    const float* Wq = (const float*)d_in[1];
    const float* Wk = (const float*)d_in[2];
    const float* Wv = (const float*)d_in[3];
    float* out = (float*)d_out;

    cudaFuncSetAttribute(qkv_mma, cudaFuncAttributeMaxDynamicSharedMemorySize, QKV_SMEM);
    cudaFuncSetAttribute(attn_mma, cudaFuncAttributeMaxDynamicSharedMemorySize, ATTN_SMEM);

    wconv_kernel<<<576, 256>>>(Wq, Wk, Wv);
    qkv_mma<<<768, 256, QKV_SMEM>>>(x);
    attn_mma<<<dim3(16, 32), 128, ATTN_SMEM>>>(out);
}

// round 7
// speedup vs baseline: 2.8350x; 1.0897x over previous
#include <cuda_runtime.h>
#include <cuda_bf16.h>
#include <math.h>
#include <cstdint>

#define NB 32
#define NT 1024
#define NC 768
#define ND 64

// ---- helpers ----
__device__ __forceinline__ uint32_t pack_bf2(float lo, float hi) {
    uint32_t r; asm("cvt.rn.bf16x2.f32 %0, %1, %2;" : "=r"(r) : "f"(hi), "f"(lo)); return r;
}
__device__ __forceinline__ float lo_bf(uint32_t h) { return __uint_as_float(h << 16); }
__device__ __forceinline__ float hi_bf(uint32_t h) { return __uint_as_float(h & 0xffff0000u); }

__device__ __forceinline__ void mma16816(float* c, const uint32_t* a, const uint32_t* b) {
    asm volatile(
        "mma.sync.aligned.m16n8k16.row.col.f32.bf16.bf16.f32 "
        "{%0,%1,%2,%3}, {%4,%5,%6,%7}, {%8,%9}, {%0,%1,%2,%3};"
        : "+f"(c[0]), "+f"(c[1]), "+f"(c[2]), "+f"(c[3])
        : "r"(a[0]), "r"(a[1]), "r"(a[2]), "r"(a[3]), "r"(b[0]), "r"(b[1]));
}
#define LDM4(r, addr) \
    asm volatile("ldmatrix.sync.aligned.m8n8.x4.shared.b16 {%0,%1,%2,%3}, [%4];" \
        : "=r"((r)[0]), "=r"((r)[1]), "=r"((r)[2]), "=r"((r)[3]) : "r"(addr))
#define CP16(dst, src) \
    asm volatile("cp.async.cg.shared.global [%0], [%1], 16;" :: "r"(dst), "l"(src))
#define CP_COMMIT() asm volatile("cp.async.commit_group;" ::: "memory")
#define CP_WAIT0()  asm volatile("cp.async.wait_group 0;" ::: "memory")

__device__ __forceinline__ uint32_t smem_u32(const void* p) {
    return (uint32_t)__cvta_generic_to_shared(p);
}

// ---- global scratch: bf16 hi/lo, 16B-chunk XOR swizzle by (row & 7) ----
__device__ __align__(16) __nv_bfloat16 g_qh[NB * NT * ND];
__device__ __align__(16) __nv_bfloat16 g_ql[NB * NT * ND];
__device__ __align__(16) __nv_bfloat16 g_kh[NB * NT * ND];
__device__ __align__(16) __nv_bfloat16 g_kl[NB * NT * ND];
__device__ __align__(16) __nv_bfloat16 g_vth[NB * ND * NT];
__device__ __align__(16) __nv_bfloat16 g_vtl[NB * ND * NT];
// W^T bf16 hi/lo, rows 0..191 = mat*64+n, [192][768]
__device__ __align__(16) __nv_bfloat16 g_Bh[192 * NC];
__device__ __align__(16) __nv_bfloat16 g_Bl[192 * NC];

// ---------------------------------------------------------------------------
// W conversion
// ---------------------------------------------------------------------------
__global__ __launch_bounds__(256) void wconv_kernel(
    const float* __restrict__ Wq, const float* __restrict__ Wk, const float* __restrict__ Wv)
{
    int idx = blockIdx.x * 256 + threadIdx.x;
    int mat = idx / 49152;
    int r = idx - mat * 49152;
    int n = r / NC;
    int k = r - n * NC;
    const float* W = (mat == 0) ? Wq : (mat == 1) ? Wk : Wv;
    float v = W[k * ND + n];
    __nv_bfloat16 h = __float2bfloat16(v);
    __nv_bfloat16 l = __float2bfloat16(v - __bfloat162float(h));
    g_Bh[idx] = h;
    g_Bl[idx] = l;
}

// ---------------------------------------------------------------------------
// Fused QKV GEMM: M=64 rows/CTA, N=192 (q|k|v), one x-convert per tile.
// grid 512, 256 threads (2M x 4N warps, warp tile 32x48). 2-stage cp.async B,
// reg-double-buffered A convert. 81920 B dynamic smem.
// ---------------------------------------------------------------------------
#define QS_AH 0
#define QS_AL 5120
#define QS_BH 10240
#define QS_BL 25600
#define QS_STAGE 40960
#define QKV_SMEM 81920

__global__ __launch_bounds__(256, 2) void qkv_mma(const float* __restrict__ x)
{
    extern __shared__ __align__(16) char sm[];
    const uint32_t smb = smem_u32(sm);

    const int tid = threadIdx.x;
    const int lane = tid & 31, w = tid >> 5;
    const int warpM = w & 1, warpN = w >> 1;
    const int g = lane >> 2, qd = lane & 3;
    const int m0 = blockIdx.x * 64;

    float acc[2][6][4];
#pragma unroll
    for (int mt = 0; mt < 2; mt++)
#pragma unroll
        for (int nt = 0; nt < 6; nt++)
#pragma unroll
            for (int i = 0; i < 4; i++) acc[mt][nt][i] = 0.f;

    const int am = tid >> 2, kq = tid & 3;
    const float* xrow = x + (size_t)(m0 + am) * NC + kq * 8;
    const uint32_t asoff = am * 80 + kq * 16;

    const uint32_t aoff = (uint32_t)((warpM * 32 + (lane & 15)) * 80 + ((lane >> 4) << 4));
    const uint32_t boff = (uint32_t)((warpN * 48 + (lane & 7) + ((lane >> 4) << 3)) * 80
                                     + (((lane >> 3) & 1) << 4));

    // prologue: A(0) -> regs, B(0) -> stage 0
    float4 rA[2][2];
    rA[0][0] = *(const float4*)(xrow);
    rA[0][1] = *(const float4*)(xrow + 4);
#pragma unroll
    for (int i = 0; i < 3; i++) {
        int id = i * 256 + tid;
        int row = id >> 2, q = id & 3;
        CP16(smb + QS_BH + row * 80 + q * 16, (const char*)(g_Bh + row * NC + q * 8));
        CP16(smb + QS_BL + row * 80 + q * 16, (const char*)(g_Bl + row * NC + q * 8));
    }
    CP_COMMIT();

#pragma unroll 2
    for (int c = 0; c < 24; c++) {
        const int s = c & 1;
        const uint32_t stb = smb + s * QS_STAGE;

        if (c + 1 < 24) {
            rA[(c + 1) & 1][0] = *(const float4*)(xrow + (c + 1) * 32);
            rA[(c + 1) & 1][1] = *(const float4*)(xrow + (c + 1) * 32 + 4);
        }
        {
            float4 f0 = rA[c & 1][0], f1 = rA[c & 1][1];
            uint32_t h0 = pack_bf2(f0.x, f0.y);
            uint32_t h1 = pack_bf2(f0.z, f0.w);
            uint32_t h2 = pack_bf2(f1.x, f1.y);
            uint32_t h3 = pack_bf2(f1.z, f1.w);
            uint32_t l0 = pack_bf2(f0.x - lo_bf(h0), f0.y - hi_bf(h0));
            uint32_t l1 = pack_bf2(f0.z - lo_bf(h1), f0.w - hi_bf(h1));
            uint32_t l2 = pack_bf2(f1.x - lo_bf(h2), f1.y - hi_bf(h2));
            uint32_t l3 = pack_bf2(f1.z - lo_bf(h3), f1.w - hi_bf(h3));
            char* base = sm + s * QS_STAGE;
            *(uint4*)(base + QS_AH + asoff) = make_uint4(h0, h1, h2, h3);
            *(uint4*)(base + QS_AL + asoff) = make_uint4(l0, l1, l2, l3);
        }

        CP_WAIT0();
        __syncthreads();

        if (c + 1 < 24) {
            const uint32_t nst = smb + (s ^ 1) * QS_STAGE;
#pragma unroll
            for (int i = 0; i < 3; i++) {
                int id = i * 256 + tid;
                int row = id >> 2, q = id & 3;
                CP16(nst + QS_BH + row * 80 + q * 16,
                     (const char*)(g_Bh + row * NC + (c + 1) * 32 + q * 8));
                CP16(nst + QS_BL + row * 80 + q * 16,
                     (const char*)(g_Bl + row * NC + (c + 1) * 32 + q * 8));
            }
            CP_COMMIT();
        }

        // ---- MMA on stage s ----
#pragma unroll
        for (int ks = 0; ks < 2; ks++) {
            uint32_t ah[2][4], al[2][4];
#pragma unroll
            for (int mt = 0; mt < 2; mt++) {
                uint32_t a = stb + QS_AH + aoff + mt * (16 * 80) + ks * 32;
                LDM4(ah[mt], a);
                LDM4(al[mt], a + (QS_AL - QS_AH));
            }
#pragma unroll
            for (int p = 0; p < 3; p++) {
                uint32_t bh4[4], bl4[4];
                uint32_t ba = stb + QS_BH + boff + p * (16 * 80) + ks * 32;
                LDM4(bh4, ba);
                LDM4(bl4, ba + (QS_BL - QS_BH));
#pragma unroll
                for (int mt = 0; mt < 2; mt++) {
                    mma16816(acc[mt][2 * p], ah[mt], bh4);
                    mma16816(acc[mt][2 * p], ah[mt], bl4);
                    mma16816(acc[mt][2 * p], al[mt], bh4);
                    mma16816(acc[mt][2 * p + 1], ah[mt], bh4 + 2);
                    mma16816(acc[mt][2 * p + 1], ah[mt], bl4 + 2);
                    mma16816(acc[mt][2 * p + 1], al[mt], bh4 + 2);
                }
            }
        }
    }
    __syncthreads();

    // ---- epilogue ----
    float* vsm = (float*)sm;   // [64 d][68 m]
#pragma unroll
    for (int nt = 0; nt < 6; nt++) {
        int col0 = warpN * 48 + nt * 8 + qd * 2;
        if (col0 < 128) {
            int mat = col0 >> 6;
            int cin = col0 & 63;
            float sc = (mat == 0) ? 0.03608439182435161f : 1.0f;
            __nv_bfloat16* dstH = (mat == 0) ? g_qh : g_kh;
            __nv_bfloat16* dstL = (mat == 0) ? g_ql : g_kl;
            int pi = cin >> 1;
            float freq = expf((float)(2 * pi) * (-9.210340371976184f / (float)ND));
            int chunk = cin >> 3;
            int bw = (cin & 7) * 2;
#pragma unroll
            for (int mt = 0; mt < 2; mt++) {
#pragma unroll
                for (int half = 0; half < 2; half++) {
                    int ml = warpM * 32 + mt * 16 + g + half * 8;
                    int r = m0 + ml;
                    float sv, cv;
                    sincosf((float)(r & (NT - 1)) * freq, &sv, &cv);
                    float e = acc[mt][nt][half * 2], o = acc[mt][nt][half * 2 + 1];
                    float re = (e * cv - o * sv) * sc;
                    float ro = (e * sv + o * cv) * sc;
                    uint32_t h = pack_bf2(re, ro);
                    uint32_t l = pack_bf2(re - lo_bf(h), ro - hi_bf(h));
                    size_t byte = (size_t)r * 128 + 16 * (chunk ^ (ml & 7)) + bw;
                    *(uint32_t*)((char*)dstH + byte) = h;
                    *(uint32_t*)((char*)dstL + byte) = l;
                }
            }
        } else {
            int cin = col0 & 63;   // d
#pragma unroll
            for (int mt = 0; mt < 2; mt++) {
#pragma unroll
                for (int half = 0; half < 2; half++) {
                    int ml = warpM * 32 + mt * 16 + g + half * 8;
                    vsm[cin * 68 + ml]       = acc[mt][nt][half * 2];
                    vsm[(cin + 1) * 68 + ml] = acc[mt][nt][half * 2 + 1];
                }
            }
        }
    }
    __syncthreads();
    {
        const int bb = m0 >> 10;
        const int t0l = m0 & (NT - 1);
#pragma unroll
        for (int i = 0; i < 8; i++) {
            int idx = tid + i * 256;     // 2048 units
            int d = idx >> 5;
            int pr = idx & 31;
            int tl = pr * 2;
            float v0 = vsm[d * 68 + tl];
            float v1 = vsm[d * 68 + tl + 1];
            uint32_t h = pack_bf2(v0, v1);
            uint32_t l = pack_bf2(v0 - lo_bf(h), v1 - hi_bf(h));
            size_t byte = ((size_t)(bb * 64 + d) * 1024 + t0l) * 2
                        + 16 * ((tl >> 3) ^ (d & 7)) + (tl & 7) * 2;
            *(uint32_t*)((char*)g_vth + byte) = h;
            *(uint32_t*)((char*)g_vtl + byte) = l;
        }
    }
}

// ---------------------------------------------------------------------------
// Flash attention: BM=128 (8 warps), BN=64, 2-stage cp.async, warp-skip on
// fully-masked diagonal iters, complementary-pair CTA schedule. grid 256.
// smem 98304 B: QH 0, QL 16384, stages at 32768 (KH 0, KL 8192, VH 16384, VL 24576)
// ---------------------------------------------------------------------------
#define AQ_H 0
#define AQ_L 16384
#define A_ST 32768
#define A_STAGE 32768
#define ATTN_SMEM 98304

__global__ __launch_bounds__(256, 2) void attn_mma(float* __restrict__ out)
{
    extern __shared__ __align__(16) char sm[];
    const uint32_t smb = smem_u32(sm);

    const int tid = threadIdx.x;
    const int lane = tid & 31, w = tid >> 5;
    const int g = lane >> 2, qd = lane & 3;
    // complementary pairing: bid and bid+148 land on the same SM -> heavy+light
    const int bid = (int)blockIdx.x;
    const int rk = (bid < 148) ? bid : 403 - bid;
    const int qt = 7 - (rk >> 5);
    const int b = rk & 31;
    const int q0 = qt * 128;
    const int jmax = 2 * qt + 1;

    // prologue: Q + KV(0)
    {
        const char* qH = (const char*)(g_qh + (size_t)(b * NT + q0) * ND);
        const char* qL = (const char*)(g_ql + (size_t)(b * NT + q0) * ND);
#pragma unroll
        for (int i = 0; i < 4; i++) {
            int idx = tid + i * 256;
            CP16(smb + AQ_H + idx * 16, qH + idx * 16);
            CP16(smb + AQ_L + idx * 16, qL + idx * 16);
        }
        const char* kH = (const char*)(g_kh + (size_t)(b * NT) * ND);
        const char* kL = (const char*)(g_kl + (size_t)(b * NT) * ND);
#pragma unroll
        for (int i = 0; i < 2; i++) {
            int idx = tid + i * 256;
            CP16(smb + A_ST + idx * 16, kH + idx * 16);
            CP16(smb + A_ST + 8192 + idx * 16, kL + idx * 16);
            int d = idx >> 3, c = idx & 7;
            size_t vb = (size_t)(b * 64 + d) * 2048 + c * 16;
            CP16(smb + A_ST + 16384 + idx * 16, (const char*)g_vth + vb);
            CP16(smb + A_ST + 24576 + idx * 16, (const char*)g_vtl + vb);
        }
        CP_COMMIT();
    }

    float o[8][4];
    float m_r[2], l_r[2];
#pragma unroll
    for (int nd = 0; nd < 8; nd++)
#pragma unroll
        for (int i = 0; i < 4; i++) o[nd][i] = 0.f;
    m_r[0] = m_r[1] = -INFINITY;
    l_r[0] = l_r[1] = 0.f;

    const uint32_t aoffQ = (uint32_t)((w * 16 + (lane & 15)) * 128);
    const uint32_t browB = (uint32_t)((lane & 7) + ((lane >> 4) << 3));
    const int lx = lane & 7, lb = (lane >> 3) & 1;
    const int rmax = q0 + w * 16 + 15;   // warp's max q-row

    CP_WAIT0();
    __syncthreads();

    for (int jt = 0; jt <= jmax; jt++) {
        const int s = jt & 1;
        const uint32_t stb = smb + A_ST + s * A_STAGE;

        if (jt > 0) { CP_WAIT0(); __syncthreads(); }

        if (jt < jmax) {   // prefetch KV(jt+1)
            const int kvn = (jt + 1) * 64;
            const uint32_t nst = smb + A_ST + (s ^ 1) * A_STAGE;
            const char* kH = (const char*)(g_kh + (size_t)(b * NT + kvn) * ND);
            const char* kL = (const char*)(g_kl + (size_t)(b * NT + kvn) * ND);
#pragma unroll
            for (int i = 0; i < 2; i++) {
                int idx = tid + i * 256;
                CP16(nst + idx * 16, kH + idx * 16);
                CP16(nst + 8192 + idx * 16, kL + idx * 16);
                int d = idx >> 3, c = idx & 7;
                size_t vb = ((size_t)(b * 64 + d) * 1024 + kvn) * 2 + c * 16;
                CP16(nst + 16384 + idx * 16, (const char*)g_vth + vb);
                CP16(nst + 24576 + idx * 16, (const char*)g_vtl + vb);
            }
            CP_COMMIT();
        }

        if (jt * 64 > rmax) continue;   // warp fully masked (only last iters)

        // ---- S = Q @ K^T ----
        float s_[8][4];
#pragma unroll
        for (int nt = 0; nt < 8; nt++)
#pragma unroll
            for (int i = 0; i < 4; i++) s_[nt][i] = 0.f;

#pragma unroll
        for (int ks = 0; ks < 4; ks++) {
            uint32_t qh4[4], ql4[4];
            uint32_t chQ = (uint32_t)(((2 * ks + (lane >> 4)) ^ lx) * 16);
            LDM4(qh4, smb + AQ_H + aoffQ + chQ);
            LDM4(ql4, smb + AQ_L + aoffQ + chQ);
            uint32_t ch = (uint32_t)(((2 * ks + lb) ^ lx) * 16);
#pragma unroll
            for (int ntp = 0; ntp < 4; ntp++) {
                uint32_t bh4[4], bl4[4];
                uint32_t ba = stb + (ntp * 16 + browB) * 128 + ch;
                LDM4(bh4, ba);
                LDM4(bl4, ba + 8192);
                mma16816(s_[2 * ntp], qh4, bh4);
                mma16816(s_[2 * ntp], qh4, bl4);
                mma16816(s_[2 * ntp], ql4, bh4);
                mma16816(s_[2 * ntp + 1], qh4, bh4 + 2);
                mma16816(s_[2 * ntp + 1], qh4, bl4 + 2);
                mma16816(s_[2 * ntp + 1], ql4, bh4 + 2);
            }
        }

        if (jt >= 2 * qt) {   // diagonal region
#pragma unroll
            for (int nt = 0; nt < 8; nt++) {
                int col = jt * 64 + nt * 8 + qd * 2;
#pragma unroll
                for (int half = 0; half < 2; half++) {
                    int row = q0 + w * 16 + g + half * 8;
                    if (col > row)     s_[nt][half * 2]     = -INFINITY;
                    if (col + 1 > row) s_[nt][half * 2 + 1] = -INFINITY;
                }
            }
        }

        // ---- online softmax ----
#pragma unroll
        for (int half = 0; half < 2; half++) {
            float mx = -INFINITY;
#pragma unroll
            for (int nt = 0; nt < 8; nt++)
                mx = fmaxf(mx, fmaxf(s_[nt][half * 2], s_[nt][half * 2 + 1]));
            mx = fmaxf(mx, __shfl_xor_sync(0xffffffffu, mx, 1));
            mx = fmaxf(mx, __shfl_xor_sync(0xffffffffu, mx, 2));
            float mn = fmaxf(m_r[half], mx);
            float alpha = __expf(m_r[half] - mn);
            m_r[half] = mn;
            float sum = 0.f;
#pragma unroll
            for (int nt = 0; nt < 8; nt++) {
                float p0 = __expf(s_[nt][half * 2] - mn);
                float p1 = __expf(s_[nt][half * 2 + 1] - mn);
                s_[nt][half * 2] = p0;
                s_[nt][half * 2 + 1] = p1;
                sum += p0 + p1;
            }
            sum += __shfl_xor_sync(0xffffffffu, sum, 1);
            sum += __shfl_xor_sync(0xffffffffu, sum, 2);
            l_r[half] = l_r[half] * alpha + sum;
#pragma unroll
            for (int nd = 0; nd < 8; nd++) {
                o[nd][half * 2] *= alpha;
                o[nd][half * 2 + 1] *= alpha;
            }
        }

        // ---- O += P @ V ----
#pragma unroll
        for (int ks = 0; ks < 4; ks++) {
            uint32_t ah[4], al[4];
            ah[0] = pack_bf2(s_[2 * ks][0], s_[2 * ks][1]);
            ah[1] = pack_bf2(s_[2 * ks][2], s_[2 * ks][3]);
            ah[2] = pack_bf2(s_[2 * ks + 1][0], s_[2 * ks + 1][1]);
            ah[3] = pack_bf2(s_[2 * ks + 1][2], s_[2 * ks + 1][3]);
            al[0] = pack_bf2(s_[2 * ks][0] - lo_bf(ah[0]), s_[2 * ks][1] - hi_bf(ah[0]));
            al[1] = pack_bf2(s_[2 * ks][2] - lo_bf(ah[1]), s_[2 * ks][3] - hi_bf(ah[1]));
            al[2] = pack_bf2(s_[2 * ks + 1][0] - lo_bf(ah[2]), s_[2 * ks + 1][1] - hi_bf(ah[2]));
            al[3] = pack_bf2(s_[2 * ks + 1][2] - lo_bf(ah[3]), s_[2 * ks + 1][3] - hi_bf(ah[3]));
            uint32_t ch = (uint32_t)(((2 * ks + lb) ^ lx) * 16);
#pragma unroll
            for (int ntp = 0; ntp < 4; ntp++) {
                uint32_t bh4[4], bl4[4];
                uint32_t ba = stb + 16384 + (ntp * 16 + browB) * 128 + ch;
                LDM4(bh4, ba);
                LDM4(bl4, ba + 8192);
                mma16816(o[2 * ntp], ah, bh4);
                mma16816(o[2 * ntp], ah, bl4);
                mma16816(o[2 * ntp], al, bh4);
                mma16816(o[2 * ntp + 1], ah, bh4 + 2);
                mma16816(o[2 * ntp + 1], ah, bl4 + 2);
                mma16816(o[2 * ntp + 1], al, bh4 + 2);
            }
        }
    }

    // epilogue
    float inv0 = 1.f / l_r[0];
    float inv1 = 1.f / l_r[1];
    int row0 = b * NT + q0 + w * 16 + g;
#pragma unroll
    for (int nd = 0; nd < 8; nd++) {
        int d = nd * 8 + qd * 2;
        *(float2*)(out + (size_t)row0 * ND + d) =
            make_float2(o[nd][0] * inv0, o[nd][1] * inv0);
        *(float2*)(out + (size_t)(row0 + 8) * ND + d) =
            make_float2(o[nd][2] * inv1, o[nd][3] * inv1);
    }
}

extern "C" void kernel_launch(void* const* d_in, const int* in_sizes, int n_in,
                              void* d_out, int out_size) {
    (void)in_sizes; (void)n_in; (void)out_size;
    const float* x  = (const float*)d_in[0];
    const float* Wq = (const float*)d_in[1];
    const float* Wk = (const float*)d_in[2];
    const float* Wv = (const float*)d_in[3];
    float* out = (float*)d_out;

    cudaFuncSetAttribute(qkv_mma, cudaFuncAttributeMaxDynamicSharedMemorySize, QKV_SMEM);
    cudaFuncSetAttribute(attn_mma, cudaFuncAttributeMaxDynamicSharedMemorySize, ATTN_SMEM);

    wconv_kernel<<<576, 256>>>(Wq, Wk, Wv);
    qkv_mma<<<512, 256, QKV_SMEM>>>(x);
    attn_mma<<<256, 256, ATTN_SMEM>>>(out);
}